// round 1
// baseline (speedup 1.0000x reference)
#include <cuda_runtime.h>
#include <math.h>
#include <stdint.h>

#define D_MODEL 512
#define INNER   768
#define NSTATE  64
#define LSEQ    2048
#define BSZ     8
#define NROWS   (BSZ * LSEQ)      // 16384
#define PROJC   (3 * INNER)       // 2304

// ---------------- scratch (device globals; no allocation allowed) ----------------
__device__ float g_h[(size_t)NROWS * D_MODEL];                 // 33.5 MB
__device__ float g_proj[(size_t)NROWS * PROJC];                // 151 MB
__device__ float g_S[NROWS + 8];
__device__ float g_dt[NROWS + 8];
__device__ float g_W[(size_t)(NROWS + 4) * NSTATE * NSTATE];   // 268 MB
__device__ float g_s[(size_t)NROWS * NSTATE];                  // 4 MB
__device__ float g_ysc[NROWS];

// ---------------- 1) LayerNorm ----------------
__global__ __launch_bounds__(128) void ln_kernel(const float* __restrict__ x,
                                                 const float* __restrict__ w,
                                                 const float* __restrict__ b) {
    int row = blockIdx.x;
    int tid = threadIdx.x;                       // 128 threads, 4 elems each
    const float4* xr = (const float4*)(x + (size_t)row * D_MODEL);
    float4 v = xr[tid];
    float s  = v.x + v.y + v.z + v.w;
    float ss = v.x*v.x + v.y*v.y + v.z*v.z + v.w*v.w;
    for (int o = 16; o; o >>= 1) {
        s  += __shfl_xor_sync(0xffffffffu, s, o);
        ss += __shfl_xor_sync(0xffffffffu, ss, o);
    }
    __shared__ float rs[4], rss[4];
    int wid = tid >> 5, lane = tid & 31;
    if (lane == 0) { rs[wid] = s; rss[wid] = ss; }
    __syncthreads();
    s  = rs[0] + rs[1] + rs[2] + rs[3];
    ss = rss[0] + rss[1] + rss[2] + rss[3];
    float mu   = s * (1.0f / 512.0f);
    float var  = ss * (1.0f / 512.0f) - mu * mu;
    float rstd = rsqrtf(var + 1e-5f);
    float4 wv = ((const float4*)w)[tid];
    float4 bv = ((const float4*)b)[tid];
    float4 o;
    o.x = (v.x - mu) * rstd * wv.x + bv.x;
    o.y = (v.y - mu) * rstd * wv.y + bv.y;
    o.z = (v.z - mu) * rstd * wv.z + bv.z;
    o.w = (v.w - mu) * rstd * wv.w + bv.w;
    ((float4*)(g_h + (size_t)row * D_MODEL))[tid] = o;
}

// ---------------- 2) GEMM1: proj = h @ W_in   (16384 x 2304 x 512) ----------------
__global__ __launch_bounds__(256) void gemm1_kernel(const float* __restrict__ Wi) {
    __shared__ __align__(16) float As[16 * 128];
    __shared__ __align__(16) float Bs[16 * 64];
    int tid = threadIdx.x;
    int n0 = blockIdx.x * 64, m0 = blockIdx.y * 128;
    int tx = tid & 15, ty = tid >> 4;
    float acc[8][4] = {};
    for (int k0 = 0; k0 < 512; k0 += 16) {
        #pragma unroll
        for (int q = 0; q < 2; q++) {
            int lin = tid + q * 256;
            int m = lin >> 2, kq = lin & 3;
            float4 v = *(const float4*)(g_h + (size_t)(m0 + m) * 512 + k0 + kq * 4);
            As[(kq * 4 + 0) * 128 + m] = v.x;
            As[(kq * 4 + 1) * 128 + m] = v.y;
            As[(kq * 4 + 2) * 128 + m] = v.z;
            As[(kq * 4 + 3) * 128 + m] = v.w;
        }
        {
            int bk = tid >> 4, bn = (tid & 15) * 4;
            *(float4*)(Bs + bk * 64 + bn) =
                *(const float4*)(Wi + (size_t)(k0 + bk) * 2304 + n0 + bn);
        }
        __syncthreads();
        #pragma unroll
        for (int kk = 0; kk < 16; kk++) {
            float4 a0 = *(float4*)(As + kk * 128 + ty * 8);
            float4 a1 = *(float4*)(As + kk * 128 + ty * 8 + 4);
            float4 bv = *(float4*)(Bs + kk * 64 + tx * 4);
            float ar[8] = {a0.x, a0.y, a0.z, a0.w, a1.x, a1.y, a1.z, a1.w};
            float br[4] = {bv.x, bv.y, bv.z, bv.w};
            #pragma unroll
            for (int r = 0; r < 8; r++)
                #pragma unroll
                for (int c = 0; c < 4; c++) acc[r][c] += ar[r] * br[c];
        }
        __syncthreads();
    }
    #pragma unroll
    for (int r = 0; r < 8; r++) {
        float4 o = {acc[r][0], acc[r][1], acc[r][2], acc[r][3]};
        *(float4*)(g_proj + (size_t)(m0 + ty * 8 + r) * 2304 + n0 + tx * 4) = o;
    }
}

// ---------------- 3) conv + silu + softplus-mean: per (b,t) emit S and dt ----------------
__global__ __launch_bounds__(256) void conv_kernel(const float* __restrict__ cw) {
    int row = blockIdx.x, tid = threadIdx.x;
    int t = row & (LSEQ - 1);
    const float* pr = g_proj + (size_t)row * PROJC;
    float sumU = 0.f, sumD = 0.f;
    #pragma unroll
    for (int j = 0; j < 3; j++) {
        int c = tid + j * 256;
        float d2 = pr[c];
        float d1 = (t >= 1) ? pr[(ptrdiff_t)c - PROJC] : 0.f;
        float d0 = (t >= 2) ? pr[(ptrdiff_t)c - 2 * PROJC] : 0.f;
        float w0 = cw[c * 3 + 0], w1 = cw[c * 3 + 1], w2 = cw[c * 3 + 2];
        float z = w0 * d0 + w1 * d1 + w2 * d2;
        float sg = 1.f / (1.f + expf(-z));
        sumU += z * sg;                                  // silu
        float dr = pr[1536 + c];
        sumD += (dr > 20.f) ? dr : log1pf(expf(dr));      // softplus
    }
    for (int o = 16; o; o >>= 1) {
        sumU += __shfl_xor_sync(0xffffffffu, sumU, o);
        sumD += __shfl_xor_sync(0xffffffffu, sumD, o);
    }
    __shared__ float r1[8], r2[8];
    if ((tid & 31) == 0) { r1[tid >> 5] = sumU; r2[tid >> 5] = sumD; }
    __syncthreads();
    if (tid == 0) {
        float a = 0.f, d = 0.f;
        #pragma unroll
        for (int w = 0; w < 8; w++) { a += r1[w]; d += r2[w]; }
        g_S[row]  = a;
        g_dt[row] = fminf(d * (1.f / 768.f) + 1e-4f, 3.f);
    }
}

// ---------------- 4) W_t = (I - dt_t A)^-1  (lower-triangular inverse, per (b,t)) ----------------
__global__ __launch_bounds__(64) void winv_kernel(const float* __restrict__ A) {
    __shared__ float As[64 * 64];
    __shared__ float Ws[64 * 64];
    int row = blockIdx.x, j = threadIdx.x;
    for (int idx = j; idx < 4096; idx += 64) { As[idx] = A[idx]; }
    float dt = g_dt[row];
    __syncthreads();
    for (int i = 0; i < 64; i++) {
        float di = 1.f - dt * As[i * 64 + i];
        float val;
        if (j < i) {
            float acc = 0.f;
            for (int m = j; m < i; m++) acc += As[i * 64 + m] * Ws[m * 64 + j];
            val = dt * acc / di;
        } else if (j == i) {
            val = 1.f / di;
        } else {
            val = 0.f;
        }
        Ws[i * 64 + j] = val;
        __syncthreads();
    }
    float* dst = g_W + (size_t)row * 4096;
    for (int idx = j; idx < 4096; idx += 64) dst[idx] = Ws[idx];
}

// ---------------- 5) sequential scan: s_t = W_t (s_{t-1} + dt*S*b) ----------------
__global__ __launch_bounds__(256) void scan_kernel(const float* __restrict__ Bm) {
    int b = blockIdx.x;
    int tid = threadIdx.x;
    int i = tid >> 2, p = tid & 3, m0 = p * 16;
    __shared__ __align__(16) float sb[64];
    __shared__ __align__(16) float sbuf[2][64];
    if (tid < 64) { sb[tid] = Bm[(size_t)tid * 768]; sbuf[0][tid] = 0.f; }
    __syncthreads();
    size_t base = (size_t)b * LSEQ;
    const float* wp = g_W + base * 4096 + (size_t)i * 64 + m0;
    float4 wbuf[4][4];
    float dtv[4], Sv[4];
    #pragma unroll
    for (int st = 0; st < 4; st++) {
        #pragma unroll
        for (int q = 0; q < 4; q++)
            wbuf[st][q] = *(const float4*)(wp + (size_t)st * 4096 + q * 4);
        dtv[st] = g_dt[base + st];
        Sv[st]  = g_S[base + st];
    }
    int cur = 0;
    for (int t = 0; t < LSEQ; t += 4) {
        #pragma unroll
        for (int st = 0; st < 4; st++) {
            int tt = t + st;
            float dtS = dtv[st] * Sv[st];
            float a0 = 0.f, a1 = 0.f, a2 = 0.f, a3 = 0.f;
            #pragma unroll
            for (int q = 0; q < 4; q++) {
                float4 w  = wbuf[st][q];
                float4 s4 = *(const float4*)&sbuf[cur][m0 + q * 4];
                float4 b4 = *(const float4*)&sb[m0 + q * 4];
                a0 += w.x * fmaf(dtS, b4.x, s4.x);
                a1 += w.y * fmaf(dtS, b4.y, s4.y);
                a2 += w.z * fmaf(dtS, b4.z, s4.z);
                a3 += w.w * fmaf(dtS, b4.w, s4.w);
            }
            float acc = (a0 + a1) + (a2 + a3);
            // prefetch W / dt / S for step tt+4 (arrays padded; OOB values unused)
            #pragma unroll
            for (int q = 0; q < 4; q++)
                wbuf[st][q] = *(const float4*)(wp + (size_t)(tt + 4) * 4096 + q * 4);
            dtv[st] = g_dt[base + tt + 4];
            Sv[st]  = g_S[base + tt + 4];
            acc += __shfl_xor_sync(0xffffffffu, acc, 1);
            acc += __shfl_xor_sync(0xffffffffu, acc, 2);
            if (p == 0) {
                sbuf[cur ^ 1][i] = acc;
                g_s[(base + tt) * 64 + i] = acc;
            }
            __syncthreads();
            cur ^= 1;
        }
    }
}

// ---------------- 6) ysc[b,t] = sum_n C[0,n] * s_t[n] ----------------
__global__ __launch_bounds__(32) void ysc_kernel(const float* __restrict__ Cm) {
    int row = blockIdx.x; int l = threadIdx.x;
    const float* sp = g_s + (size_t)row * 64;
    float v = sp[l] * Cm[l] + sp[32 + l] * Cm[32 + l];
    for (int o = 16; o; o >>= 1) v += __shfl_xor_sync(0xffffffffu, v, o);
    if (l == 0) g_ysc[row] = v;
}

// ---------------- 7) GEMM2: out = x + ysc * (sigmoid(gate) @ W_out) ----------------
__global__ __launch_bounds__(256) void gemm2_kernel(const float* __restrict__ x,
                                                    const float* __restrict__ Wo,
                                                    float* __restrict__ out) {
    __shared__ __align__(16) float As[16 * 128];
    __shared__ __align__(16) float Bs[16 * 64];
    int tid = threadIdx.x;
    int n0 = blockIdx.x * 64, m0 = blockIdx.y * 128;
    int tx = tid & 15, ty = tid >> 4;
    float acc[8][4] = {};
    for (int k0 = 0; k0 < 768; k0 += 16) {
        #pragma unroll
        for (int q = 0; q < 2; q++) {
            int lin = tid + q * 256;
            int m = lin >> 2, kq = lin & 3;
            float4 v = *(const float4*)(g_proj + (size_t)(m0 + m) * 2304 + 768 + k0 + kq * 4);
            As[(kq * 4 + 0) * 128 + m] = 1.f / (1.f + expf(-v.x));
            As[(kq * 4 + 1) * 128 + m] = 1.f / (1.f + expf(-v.y));
            As[(kq * 4 + 2) * 128 + m] = 1.f / (1.f + expf(-v.z));
            As[(kq * 4 + 3) * 128 + m] = 1.f / (1.f + expf(-v.w));
        }
        {
            int bk = tid >> 4, bn = (tid & 15) * 4;
            *(float4*)(Bs + bk * 64 + bn) =
                *(const float4*)(Wo + (size_t)(k0 + bk) * 512 + n0 + bn);
        }
        __syncthreads();
        #pragma unroll
        for (int kk = 0; kk < 16; kk++) {
            float4 a0 = *(float4*)(As + kk * 128 + ty * 8);
            float4 a1 = *(float4*)(As + kk * 128 + ty * 8 + 4);
            float4 bv = *(float4*)(Bs + kk * 64 + tx * 4);
            float ar[8] = {a0.x, a0.y, a0.z, a0.w, a1.x, a1.y, a1.z, a1.w};
            float br[4] = {bv.x, bv.y, bv.z, bv.w};
            #pragma unroll
            for (int r = 0; r < 8; r++)
                #pragma unroll
                for (int c = 0; c < 4; c++) acc[r][c] += ar[r] * br[c];
        }
        __syncthreads();
    }
    #pragma unroll
    for (int r = 0; r < 8; r++) {
        int row = m0 + ty * 8 + r;
        float ys = g_ysc[row];
        float4 xv = *(const float4*)(x + (size_t)row * 512 + n0 + tx * 4);
        float4 o;
        o.x = xv.x + ys * acc[r][0];
        o.y = xv.y + ys * acc[r][1];
        o.z = xv.z + ys * acc[r][2];
        o.w = xv.w + ys * acc[r][3];
        *(float4*)(out + (size_t)row * 512 + n0 + tx * 4) = o;
    }
}

// ---------------- launch ----------------
extern "C" void kernel_launch(void* const* d_in, const int* in_sizes, int n_in,
                              void* d_out, int out_size) {
    const float* x  = (const float*)d_in[0];
    const float* nw = (const float*)d_in[1];
    const float* nb = (const float*)d_in[2];
    const float* Wi = (const float*)d_in[3];
    const float* cw = (const float*)d_in[4];
    const float* A  = (const float*)d_in[5];
    const float* Bm = (const float*)d_in[6];
    const float* Cm = (const float*)d_in[7];
    const float* Wo = (const float*)d_in[8];
    float* out = (float*)d_out;

    ln_kernel<<<NROWS, 128>>>(x, nw, nb);
    gemm1_kernel<<<dim3(36, 128), 256>>>(Wi);
    conv_kernel<<<NROWS, 256>>>(cw);
    winv_kernel<<<NROWS, 64>>>(A);
    scan_kernel<<<BSZ, 256>>>(Bm);
    ysc_kernel<<<NROWS, 32>>>(Cm);
    gemm2_kernel<<<dim3(8, 128), 256>>>(x, Wo, out);
}

// round 2
// speedup vs baseline: 1.9410x; 1.9410x over previous
#include <cuda_runtime.h>
#include <math.h>
#include <stdint.h>

#define D_MODEL 512
#define INNER   768
#define NSTATE  64
#define LSEQ    2048
#define BSZ     8
#define NROWS   (BSZ * LSEQ)      // 16384
#define PROJC   (3 * INNER)       // 2304

// ---------------- scratch (device globals; no allocation allowed) ----------------
__device__ float g_h[(size_t)NROWS * D_MODEL];                 // 33.5 MB
__device__ float g_proj[(size_t)NROWS * PROJC];                // 151 MB
__device__ float g_S[NROWS + 8];
__device__ float g_dt[NROWS + 8];
__device__ float g_ysc[NROWS];

// ---------------- 1) LayerNorm ----------------
__global__ __launch_bounds__(128) void ln_kernel(const float* __restrict__ x,
                                                 const float* __restrict__ w,
                                                 const float* __restrict__ b) {
    int row = blockIdx.x;
    int tid = threadIdx.x;                       // 128 threads, 4 elems each
    const float4* xr = (const float4*)(x + (size_t)row * D_MODEL);
    float4 v = xr[tid];
    float s  = v.x + v.y + v.z + v.w;
    float ss = v.x*v.x + v.y*v.y + v.z*v.z + v.w*v.w;
    for (int o = 16; o; o >>= 1) {
        s  += __shfl_xor_sync(0xffffffffu, s, o);
        ss += __shfl_xor_sync(0xffffffffu, ss, o);
    }
    __shared__ float rs[4], rss[4];
    int wid = tid >> 5, lane = tid & 31;
    if (lane == 0) { rs[wid] = s; rss[wid] = ss; }
    __syncthreads();
    s  = rs[0] + rs[1] + rs[2] + rs[3];
    ss = rss[0] + rss[1] + rss[2] + rss[3];
    float mu   = s * (1.0f / 512.0f);
    float var  = ss * (1.0f / 512.0f) - mu * mu;
    float rstd = rsqrtf(var + 1e-5f);
    float4 wv = ((const float4*)w)[tid];
    float4 bv = ((const float4*)b)[tid];
    float4 o;
    o.x = (v.x - mu) * rstd * wv.x + bv.x;
    o.y = (v.y - mu) * rstd * wv.y + bv.y;
    o.z = (v.z - mu) * rstd * wv.z + bv.z;
    o.w = (v.w - mu) * rstd * wv.w + bv.w;
    ((float4*)(g_h + (size_t)row * D_MODEL))[tid] = o;
}

// ---------------- 2) GEMM1: proj = h @ W_in   (16384 x 2304 x 512) ----------------
__global__ __launch_bounds__(256) void gemm1_kernel(const float* __restrict__ Wi) {
    __shared__ __align__(16) float As[16 * 128];
    __shared__ __align__(16) float Bs[16 * 64];
    int tid = threadIdx.x;
    int n0 = blockIdx.x * 64, m0 = blockIdx.y * 128;
    int tx = tid & 15, ty = tid >> 4;
    float acc[8][4] = {};
    for (int k0 = 0; k0 < 512; k0 += 16) {
        #pragma unroll
        for (int q = 0; q < 2; q++) {
            int lin = tid + q * 256;
            int m = lin >> 2, kq = lin & 3;
            float4 v = *(const float4*)(g_h + (size_t)(m0 + m) * 512 + k0 + kq * 4);
            As[(kq * 4 + 0) * 128 + m] = v.x;
            As[(kq * 4 + 1) * 128 + m] = v.y;
            As[(kq * 4 + 2) * 128 + m] = v.z;
            As[(kq * 4 + 3) * 128 + m] = v.w;
        }
        {
            int bk = tid >> 4, bn = (tid & 15) * 4;
            *(float4*)(Bs + bk * 64 + bn) =
                *(const float4*)(Wi + (size_t)(k0 + bk) * 2304 + n0 + bn);
        }
        __syncthreads();
        #pragma unroll
        for (int kk = 0; kk < 16; kk++) {
            float4 a0 = *(float4*)(As + kk * 128 + ty * 8);
            float4 a1 = *(float4*)(As + kk * 128 + ty * 8 + 4);
            float4 bv = *(float4*)(Bs + kk * 64 + tx * 4);
            float ar[8] = {a0.x, a0.y, a0.z, a0.w, a1.x, a1.y, a1.z, a1.w};
            float br[4] = {bv.x, bv.y, bv.z, bv.w};
            #pragma unroll
            for (int r = 0; r < 8; r++)
                #pragma unroll
                for (int c = 0; c < 4; c++) acc[r][c] += ar[r] * br[c];
        }
        __syncthreads();
    }
    #pragma unroll
    for (int r = 0; r < 8; r++) {
        float4 o = {acc[r][0], acc[r][1], acc[r][2], acc[r][3]};
        *(float4*)(g_proj + (size_t)(m0 + ty * 8 + r) * 2304 + n0 + tx * 4) = o;
    }
}

// ---------------- 3) conv + silu + softplus-mean: per (b,t) emit S and dt ----------------
__global__ __launch_bounds__(256) void conv_kernel(const float* __restrict__ cw) {
    int row = blockIdx.x, tid = threadIdx.x;
    int t = row & (LSEQ - 1);
    const float* pr = g_proj + (size_t)row * PROJC;
    float sumU = 0.f, sumD = 0.f;
    #pragma unroll
    for (int j = 0; j < 3; j++) {
        int c = tid + j * 256;
        float d2 = pr[c];
        float d1 = (t >= 1) ? pr[(ptrdiff_t)c - PROJC] : 0.f;
        float d0 = (t >= 2) ? pr[(ptrdiff_t)c - 2 * PROJC] : 0.f;
        float w0 = cw[c * 3 + 0], w1 = cw[c * 3 + 1], w2 = cw[c * 3 + 2];
        float z = w0 * d0 + w1 * d1 + w2 * d2;
        float sg = 1.f / (1.f + expf(-z));
        sumU += z * sg;                                  // silu
        float dr = pr[1536 + c];
        sumD += (dr > 20.f) ? dr : log1pf(expf(dr));      // softplus
    }
    for (int o = 16; o; o >>= 1) {
        sumU += __shfl_xor_sync(0xffffffffu, sumU, o);
        sumD += __shfl_xor_sync(0xffffffffu, sumD, o);
    }
    __shared__ float r1[8], r2[8];
    if ((tid & 31) == 0) { r1[tid >> 5] = sumU; r2[tid >> 5] = sumD; }
    __syncthreads();
    if (tid == 0) {
        float a = 0.f, d = 0.f;
        #pragma unroll
        for (int w = 0; w < 8; w++) { a += r1[w]; d += r2[w]; }
        g_S[row]  = a;
        g_dt[row] = fminf(d * (1.f / 768.f) + 1e-4f, 3.f);
    }
}

// ---------------- 4) fused scan: O(N) rank-1 triangular solve per step + ysc ----------------
// A = -tril(e e^T), e_i = (-1)^i sqrt(2i+1). Solve (I + dt tril(e e^T)) x = r via
// p_i = p_{i-1}/d_i + e_i r_i / d_i  (warp scan on (1/d, e r/d) pairs), d_i = 1 + dt e_i^2,
// x_i = (r_i - dt e_i p_{i-1})/d_i.  One warp per batch; 2 states per lane.
__global__ __launch_bounds__(32) void scan2_kernel(const float* __restrict__ Bm,
                                                   const float* __restrict__ Cm,
                                                   const float* __restrict__ A) {
    int b = blockIdx.x, l = threadIdx.x;
    int i0 = 2 * l, i1 = 2 * l + 1;
    float e0 =  sqrtf(-A[i0 * 64 + i0]);   // even index: +sqrt(2i+1)
    float e1 = -sqrtf(-A[i1 * 64 + i1]);   // odd index:  -sqrt(2i+1)
    float e0sq = e0 * e0, e1sq = e1 * e1;
    float bv0 = Bm[(size_t)i0 * INNER], bv1 = Bm[(size_t)i1 * INNER];
    float C0 = Cm[i0], C1 = Cm[i1];
    size_t base = (size_t)b * LSEQ;
    float s0 = 0.f, s1 = 0.f;
    const int PF = 4;
    float dtb[PF], Sb[PF];
    #pragma unroll
    for (int j = 0; j < PF; j++) { dtb[j] = g_dt[base + j]; Sb[j] = g_S[base + j]; }
    for (int t0 = 0; t0 < LSEQ; t0 += PF) {
        #pragma unroll
        for (int j = 0; j < PF; j++) {
            int t = t0 + j;
            float dt = dtb[j], S = Sb[j];
            dtb[j] = g_dt[base + t + PF];           // prefetch (arrays padded)
            Sb[j]  = g_S[base + t + PF];
            // per-step, state-independent coefficients (off the serial chain)
            float invd0 = __fdividef(1.f, fmaf(dt, e0sq, 1.f));
            float invd1 = __fdividef(1.f, fmaf(dt, e1sq, 1.f));
            float k0 = e0 * invd0, k1 = e1 * invd1;
            float m0 = dt * k0,    m1 = dt * k1;
            float Aloc = invd0 * invd1;
            float dtS = dt * S;
            // r = s + dt*S*b
            float r0 = fmaf(dtS, bv0, s0);
            float r1 = fmaf(dtS, bv1, s1);
            // local 2-element compose: (A,B) = (invd0*invd1, invd1*(k0 r0) + k1 r1)
            float Bc = fmaf(invd1, k0 * r0, k1 * r1);
            float Ac = Aloc;
            // warp inclusive scan of linear-recurrence segments
            #pragma unroll
            for (int ofs = 1; ofs < 32; ofs <<= 1) {
                float Au = __shfl_up_sync(0xffffffffu, Ac, ofs);
                float Bu = __shfl_up_sync(0xffffffffu, Bc, ofs);
                if (l >= ofs) { Bc = fmaf(Ac, Bu, Bc); Ac *= Au; }
            }
            float pex = __shfl_up_sync(0xffffffffu, Bc, 1);   // p_{2l-1}
            if (l == 0) pex = 0.f;
            float x0 = fmaf(-m0, pex, invd0 * r0);
            float p0 = fmaf(invd0, pex, k0 * r0);             // p_{2l}
            float x1 = fmaf(-m1, p0, invd1 * r1);
            s0 = x0; s1 = x1;
            // ysc_t = sum_i C_i x_i (off the t->t+1 chain)
            float wv = C0 * x0 + C1 * x1;
            #pragma unroll
            for (int o = 16; o; o >>= 1) wv += __shfl_xor_sync(0xffffffffu, wv, o);
            if (l == 0) g_ysc[base + t] = wv;
        }
    }
}

// ---------------- 5) GEMM2: out = x + ysc * (sigmoid(gate) @ W_out) ----------------
__global__ __launch_bounds__(256) void gemm2_kernel(const float* __restrict__ x,
                                                    const float* __restrict__ Wo,
                                                    float* __restrict__ out) {
    __shared__ __align__(16) float As[16 * 128];
    __shared__ __align__(16) float Bs[16 * 64];
    int tid = threadIdx.x;
    int n0 = blockIdx.x * 64, m0 = blockIdx.y * 128;
    int tx = tid & 15, ty = tid >> 4;
    float acc[8][4] = {};
    for (int k0 = 0; k0 < 768; k0 += 16) {
        #pragma unroll
        for (int q = 0; q < 2; q++) {
            int lin = tid + q * 256;
            int m = lin >> 2, kq = lin & 3;
            float4 v = *(const float4*)(g_proj + (size_t)(m0 + m) * 2304 + 768 + k0 + kq * 4);
            As[(kq * 4 + 0) * 128 + m] = 1.f / (1.f + expf(-v.x));
            As[(kq * 4 + 1) * 128 + m] = 1.f / (1.f + expf(-v.y));
            As[(kq * 4 + 2) * 128 + m] = 1.f / (1.f + expf(-v.z));
            As[(kq * 4 + 3) * 128 + m] = 1.f / (1.f + expf(-v.w));
        }
        {
            int bk = tid >> 4, bn = (tid & 15) * 4;
            *(float4*)(Bs + bk * 64 + bn) =
                *(const float4*)(Wo + (size_t)(k0 + bk) * 512 + n0 + bn);
        }
        __syncthreads();
        #pragma unroll
        for (int kk = 0; kk < 16; kk++) {
            float4 a0 = *(float4*)(As + kk * 128 + ty * 8);
            float4 a1 = *(float4*)(As + kk * 128 + ty * 8 + 4);
            float4 bv = *(float4*)(Bs + kk * 64 + tx * 4);
            float ar[8] = {a0.x, a0.y, a0.z, a0.w, a1.x, a1.y, a1.z, a1.w};
            float br[4] = {bv.x, bv.y, bv.z, bv.w};
            #pragma unroll
            for (int r = 0; r < 8; r++)
                #pragma unroll
                for (int c = 0; c < 4; c++) acc[r][c] += ar[r] * br[c];
        }
        __syncthreads();
    }
    #pragma unroll
    for (int r = 0; r < 8; r++) {
        int row = m0 + ty * 8 + r;
        float ys = g_ysc[row];
        float4 xv = *(const float4*)(x + (size_t)row * 512 + n0 + tx * 4);
        float4 o;
        o.x = xv.x + ys * acc[r][0];
        o.y = xv.y + ys * acc[r][1];
        o.z = xv.z + ys * acc[r][2];
        o.w = xv.w + ys * acc[r][3];
        *(float4*)(out + (size_t)row * 512 + n0 + tx * 4) = o;
    }
}

// ---------------- launch ----------------
extern "C" void kernel_launch(void* const* d_in, const int* in_sizes, int n_in,
                              void* d_out, int out_size) {
    const float* x  = (const float*)d_in[0];
    const float* nw = (const float*)d_in[1];
    const float* nb = (const float*)d_in[2];
    const float* Wi = (const float*)d_in[3];
    const float* cw = (const float*)d_in[4];
    const float* A  = (const float*)d_in[5];
    const float* Bm = (const float*)d_in[6];
    const float* Cm = (const float*)d_in[7];
    const float* Wo = (const float*)d_in[8];
    float* out = (float*)d_out;

    ln_kernel<<<NROWS, 128>>>(x, nw, nb);
    gemm1_kernel<<<dim3(36, 128), 256>>>(Wi);
    conv_kernel<<<NROWS, 256>>>(cw);
    scan2_kernel<<<BSZ, 32>>>(Bm, Cm, A);
    gemm2_kernel<<<dim3(8, 128), 256>>>(x, Wo, out);
}

// round 4
// speedup vs baseline: 4.1810x; 2.1540x over previous
#include <cuda_runtime.h>
#include <math.h>
#include <stdint.h>

#define D_MODEL 512
#define INNER   768
#define NSTATE  64
#define LSEQ    2048
#define BSZ     8
#define NROWS   (BSZ * LSEQ)      // 16384
#define PROJC   (3 * INNER)       // 2304

// ---------------- scratch ----------------
__device__ float g_h[(size_t)NROWS * D_MODEL];
__device__ float g_proj[(size_t)NROWS * PROJC];
__device__ float g_gate[(size_t)NROWS * INNER];     // sigmoid(gate)
__device__ float g_WiT[(size_t)PROJC * D_MODEL];    // [2304][512]
__device__ float g_WoT[(size_t)D_MODEL * INNER];    // [512][768]
__device__ float g_S[NROWS + 8];
__device__ float g_dt[NROWS + 8];
__device__ float g_xs[(size_t)NROWS * NSTATE];      // scan states
__device__ float g_ysc[NROWS];

// ---------------- helpers ----------------
__device__ __forceinline__ uint32_t smem_u32(const void* p) {
    uint32_t a;
    asm("{ .reg .u64 t; cvta.to.shared.u64 t, %1; cvt.u32.u64 %0, t; }" : "=r"(a) : "l"(p));
    return a;
}
__device__ __forceinline__ uint32_t f2tf(float f) {
    uint32_t r;
    asm("cvt.rna.tf32.f32 %0, %1;" : "=r"(r) : "f"(f));
    return r;
}
#define CP16(dst, src) \
    asm volatile("cp.async.cg.shared.global [%0], [%1], 16;" :: "r"(dst), "l"(src))
#define CP_COMMIT() asm volatile("cp.async.commit_group;" ::: "memory")
#define CP_WAIT(n)  asm volatile("cp.async.wait_group %0;" :: "n"(n) : "memory")

__device__ __forceinline__ void mma_tf32(float* d, const uint32_t* a, const uint32_t* b) {
    asm volatile("mma.sync.aligned.m16n8k8.row.col.f32.tf32.tf32.f32 "
                 "{%0,%1,%2,%3}, {%4,%5,%6,%7}, {%8,%9}, {%0,%1,%2,%3};"
                 : "+f"(d[0]), "+f"(d[1]), "+f"(d[2]), "+f"(d[3])
                 : "r"(a[0]), "r"(a[1]), "r"(a[2]), "r"(a[3]), "r"(b[0]), "r"(b[1]));
}

#define SMSTRIDE 20   // 16 + 4 pad: conflict-free for fragment LDS pattern

// ---------------- transpose: dst[C][R] = src[R][C] ----------------
__global__ __launch_bounds__(256) void transpose_kernel(const float* __restrict__ src,
                                                        float* __restrict__ dst,
                                                        int R, int C) {
    __shared__ float tile[32][33];
    int c0 = blockIdx.x * 32, r0 = blockIdx.y * 32;
    int x = threadIdx.x & 31, y = threadIdx.x >> 5;
    #pragma unroll
    for (int j = 0; j < 32; j += 8) tile[y + j][x] = src[(size_t)(r0 + y + j) * C + c0 + x];
    __syncthreads();
    #pragma unroll
    for (int j = 0; j < 32; j += 8) dst[(size_t)(c0 + y + j) * R + r0 + x] = tile[x][y + j];
}

// ---------------- LayerNorm ----------------
__global__ __launch_bounds__(128) void ln_kernel(const float* __restrict__ x,
                                                 const float* __restrict__ w,
                                                 const float* __restrict__ b) {
    int row = blockIdx.x, tid = threadIdx.x;
    const float4* xr = (const float4*)(x + (size_t)row * D_MODEL);
    float4 v = xr[tid];
    float s  = v.x + v.y + v.z + v.w;
    float ss = v.x*v.x + v.y*v.y + v.z*v.z + v.w*v.w;
    for (int o = 16; o; o >>= 1) {
        s  += __shfl_xor_sync(0xffffffffu, s, o);
        ss += __shfl_xor_sync(0xffffffffu, ss, o);
    }
    __shared__ float rs[4], rss[4];
    int wid = tid >> 5, lane = tid & 31;
    if (lane == 0) { rs[wid] = s; rss[wid] = ss; }
    __syncthreads();
    s  = rs[0] + rs[1] + rs[2] + rs[3];
    ss = rss[0] + rss[1] + rss[2] + rss[3];
    float mu = s * (1.0f / 512.0f);
    float rstd = rsqrtf(ss * (1.0f / 512.0f) - mu * mu + 1e-5f);
    float4 wv = ((const float4*)w)[tid];
    float4 bv = ((const float4*)b)[tid];
    float4 o;
    o.x = (v.x - mu) * rstd * wv.x + bv.x;
    o.y = (v.y - mu) * rstd * wv.y + bv.y;
    o.z = (v.z - mu) * rstd * wv.z + bv.z;
    o.w = (v.w - mu) * rstd * wv.w + bv.w;
    ((float4*)(g_h + (size_t)row * D_MODEL))[tid] = o;
}

// ---------------- GEMM1: g_proj = g_h @ WiT^T  (tf32 mma.sync, cp.async) ----------------
// grid (18, 128): n0 = bx*128, m0 = by*128. K=512, 32 stages of 16.
__global__ __launch_bounds__(256, 2) void gemm1_mma() {
    __shared__ float smA[2][128 * SMSTRIDE];
    __shared__ float smB[2][128 * SMSTRIDE];
    int tid = threadIdx.x, wid = tid >> 5, lane = tid & 31;
    int m0 = blockIdx.y * 128, n0 = blockIdx.x * 128;
    int wm = (wid >> 2) * 64, wn = (wid & 3) * 32;
    int grp = lane >> 2, tg = lane & 3;
    uint32_t bA = smem_u32(smA), bB = smem_u32(smB);

    int r0 = tid >> 2, kc0 = (tid & 3) * 4;              // chunk 0
    int r1 = (tid + 256) >> 2, kc1 = ((tid + 256) & 3) * 4;
    const int NS = 32;

    float acc[4][4][4] = {};

    #pragma unroll 1
    for (int s = 0; s < 2; s++) {
        int k0 = s * 16;
        uint32_t ao = (uint32_t)(s * 128 * SMSTRIDE * 4);
        CP16(bA + ao + (r0 * SMSTRIDE + kc0) * 4, g_h + (size_t)(m0 + r0) * 512 + k0 + kc0);
        CP16(bA + ao + (r1 * SMSTRIDE + kc1) * 4, g_h + (size_t)(m0 + r1) * 512 + k0 + kc1);
        CP16(bB + ao + (r0 * SMSTRIDE + kc0) * 4, g_WiT + (size_t)(n0 + r0) * 512 + k0 + kc0);
        CP16(bB + ao + (r1 * SMSTRIDE + kc1) * 4, g_WiT + (size_t)(n0 + r1) * 512 + k0 + kc1);
        CP_COMMIT();
    }
    for (int s = 0; s < NS; s++) {
        int buf = s & 1;
        CP_WAIT(1);
        __syncthreads();
        const float* As = smA[buf];
        const float* Bs = smB[buf];
        #pragma unroll
        for (int ks = 0; ks < 2; ks++) {
            int kb = ks * 8;
            uint32_t af[4][4], bf[4][2];
            #pragma unroll
            for (int mi = 0; mi < 4; mi++) {
                int rr = wm + mi * 16 + grp;
                af[mi][0] = f2tf(As[rr * SMSTRIDE + kb + tg]);
                af[mi][1] = f2tf(As[(rr + 8) * SMSTRIDE + kb + tg]);
                af[mi][2] = f2tf(As[rr * SMSTRIDE + kb + tg + 4]);
                af[mi][3] = f2tf(As[(rr + 8) * SMSTRIDE + kb + tg + 4]);
            }
            #pragma unroll
            for (int ni = 0; ni < 4; ni++) {
                int cc = wn + ni * 8 + grp;
                bf[ni][0] = f2tf(Bs[cc * SMSTRIDE + kb + tg]);
                bf[ni][1] = f2tf(Bs[cc * SMSTRIDE + kb + tg + 4]);
            }
            #pragma unroll
            for (int mi = 0; mi < 4; mi++)
                #pragma unroll
                for (int ni = 0; ni < 4; ni++)
                    mma_tf32(acc[mi][ni], af[mi], bf[ni]);
        }
        __syncthreads();
        if (s + 2 < NS) {
            int k0 = (s + 2) * 16;
            uint32_t ao = (uint32_t)(buf * 128 * SMSTRIDE * 4);
            CP16(bA + ao + (r0 * SMSTRIDE + kc0) * 4, g_h + (size_t)(m0 + r0) * 512 + k0 + kc0);
            CP16(bA + ao + (r1 * SMSTRIDE + kc1) * 4, g_h + (size_t)(m0 + r1) * 512 + k0 + kc1);
            CP16(bB + ao + (r0 * SMSTRIDE + kc0) * 4, g_WiT + (size_t)(n0 + r0) * 512 + k0 + kc0);
            CP16(bB + ao + (r1 * SMSTRIDE + kc1) * 4, g_WiT + (size_t)(n0 + r1) * 512 + k0 + kc1);
        }
        CP_COMMIT();
    }
    #pragma unroll
    for (int mi = 0; mi < 4; mi++)
        #pragma unroll
        for (int ni = 0; ni < 4; ni++) {
            int rr = m0 + wm + mi * 16 + grp;
            int cc = n0 + wn + ni * 8 + 2 * tg;
            float2 lo = {acc[mi][ni][0], acc[mi][ni][1]};
            float2 hi = {acc[mi][ni][2], acc[mi][ni][3]};
            *(float2*)&g_proj[(size_t)rr * PROJC + cc] = lo;
            *(float2*)&g_proj[(size_t)(rr + 8) * PROJC + cc] = hi;
        }
}

// ---------------- conv + silu + softplus-mean + gate sigmoid ----------------
__global__ __launch_bounds__(256) void conv_kernel(const float* __restrict__ cw) {
    int row = blockIdx.x, tid = threadIdx.x;
    int t = row & (LSEQ - 1);
    const float* pr = g_proj + (size_t)row * PROJC;
    float* gt = g_gate + (size_t)row * INNER;
    float sumU = 0.f, sumD = 0.f;
    #pragma unroll
    for (int j = 0; j < 3; j++) {
        int c = tid + j * 256;
        float d2 = pr[c];
        float d1 = (t >= 1) ? pr[(ptrdiff_t)c - PROJC] : 0.f;
        float d0 = (t >= 2) ? pr[(ptrdiff_t)c - 2 * PROJC] : 0.f;
        float z = cw[c*3] * d0 + cw[c*3+1] * d1 + cw[c*3+2] * d2;
        sumU += z / (1.f + expf(-z));
        float dr = pr[1536 + c];
        sumD += (dr > 20.f) ? dr : log1pf(expf(dr));
        float gv = pr[768 + c];
        gt[c] = 1.f / (1.f + expf(-gv));
    }
    for (int o = 16; o; o >>= 1) {
        sumU += __shfl_xor_sync(0xffffffffu, sumU, o);
        sumD += __shfl_xor_sync(0xffffffffu, sumD, o);
    }
    __shared__ float r1[8], r2[8];
    if ((tid & 31) == 0) { r1[tid >> 5] = sumU; r2[tid >> 5] = sumD; }
    __syncthreads();
    if (tid == 0) {
        float a = 0.f, d = 0.f;
        #pragma unroll
        for (int w = 0; w < 8; w++) { a += r1[w]; d += r2[w]; }
        g_S[row]  = a;
        g_dt[row] = fminf(d * (1.f / 768.f) + 1e-4f, 3.f);
    }
}

// ---------------- fused scan: O(N) rank-1 triangular solve per step ----------------
__global__ __launch_bounds__(32) void scan2_kernel(const float* __restrict__ Bm,
                                                   const float* __restrict__ A) {
    int b = blockIdx.x, l = threadIdx.x;
    int i0 = 2 * l, i1 = 2 * l + 1;
    float e0 =  sqrtf(-A[i0 * 64 + i0]);
    float e1 = -sqrtf(-A[i1 * 64 + i1]);
    float e0sq = e0 * e0, e1sq = e1 * e1;
    float bv0 = Bm[(size_t)i0 * INNER], bv1 = Bm[(size_t)i1 * INNER];
    size_t base = (size_t)b * LSEQ;
    float s0 = 0.f, s1 = 0.f;
    const int PF = 4;
    float dtb[PF], Sb[PF];
    #pragma unroll
    for (int j = 0; j < PF; j++) { dtb[j] = g_dt[base + j]; Sb[j] = g_S[base + j]; }
    for (int t0 = 0; t0 < LSEQ; t0 += PF) {
        #pragma unroll
        for (int j = 0; j < PF; j++) {
            int t = t0 + j;
            float dt = dtb[j], S = Sb[j];
            dtb[j] = g_dt[base + t + PF];
            Sb[j]  = g_S[base + t + PF];
            float invd0 = __fdividef(1.f, fmaf(dt, e0sq, 1.f));
            float invd1 = __fdividef(1.f, fmaf(dt, e1sq, 1.f));
            float k0 = e0 * invd0, k1 = e1 * invd1;
            float m0 = dt * k0,    m1 = dt * k1;
            float dtS = dt * S;
            float r0 = fmaf(dtS, bv0, s0);
            float r1 = fmaf(dtS, bv1, s1);
            float Bc = fmaf(invd1, k0 * r0, k1 * r1);
            float Ac = invd0 * invd1;
            #pragma unroll
            for (int ofs = 1; ofs < 32; ofs <<= 1) {
                float Au = __shfl_up_sync(0xffffffffu, Ac, ofs);
                float Bu = __shfl_up_sync(0xffffffffu, Bc, ofs);
                if (l >= ofs) { Bc = fmaf(Ac, Bu, Bc); Ac *= Au; }
            }
            float pex = __shfl_up_sync(0xffffffffu, Bc, 1);
            if (l == 0) pex = 0.f;
            float x0 = fmaf(-m0, pex, invd0 * r0);
            float p0 = fmaf(invd0, pex, k0 * r0);
            float x1 = fmaf(-m1, p0, invd1 * r1);
            s0 = x0; s1 = x1;
            float2 st = {x0, x1};
            *(float2*)&g_xs[(base + t) * 64 + 2 * l] = st;   // off-chain
        }
    }
}

// ---------------- ysc[b,t] = C . x_t ----------------
__global__ __launch_bounds__(256) void ysc_kernel(const float* __restrict__ Cm) {
    int row = blockIdx.x * 8 + (threadIdx.x >> 5);
    int l = threadIdx.x & 31;
    const float* sp = g_xs + (size_t)row * 64;
    float v = sp[l] * Cm[l] + sp[32 + l] * Cm[32 + l];
    for (int o = 16; o; o >>= 1) v += __shfl_xor_sync(0xffffffffu, v, o);
    if (l == 0) g_ysc[row] = v;
}

// ---------------- GEMM2: out = x + ysc * (g_gate @ WoT^T) ----------------
// grid (4, 128): n0 = bx*128, m0 = by*128. K=768, 48 stages.
__global__ __launch_bounds__(256, 2) void gemm2_mma(const float* __restrict__ x,
                                                    float* __restrict__ out) {
    __shared__ float smA[2][128 * SMSTRIDE];
    __shared__ float smB[2][128 * SMSTRIDE];
    int tid = threadIdx.x, wid = tid >> 5, lane = tid & 31;
    int m0 = blockIdx.y * 128, n0 = blockIdx.x * 128;
    int wm = (wid >> 2) * 64, wn = (wid & 3) * 32;
    int grp = lane >> 2, tg = lane & 3;
    uint32_t bA = smem_u32(smA), bB = smem_u32(smB);

    int r0 = tid >> 2, kc0 = (tid & 3) * 4;
    int r1 = (tid + 256) >> 2, kc1 = ((tid + 256) & 3) * 4;
    const int NS = 48;

    float acc[4][4][4] = {};

    #pragma unroll 1
    for (int s = 0; s < 2; s++) {
        int k0 = s * 16;
        uint32_t ao = (uint32_t)(s * 128 * SMSTRIDE * 4);
        CP16(bA + ao + (r0 * SMSTRIDE + kc0) * 4, g_gate + (size_t)(m0 + r0) * INNER + k0 + kc0);
        CP16(bA + ao + (r1 * SMSTRIDE + kc1) * 4, g_gate + (size_t)(m0 + r1) * INNER + k0 + kc1);
        CP16(bB + ao + (r0 * SMSTRIDE + kc0) * 4, g_WoT + (size_t)(n0 + r0) * INNER + k0 + kc0);
        CP16(bB + ao + (r1 * SMSTRIDE + kc1) * 4, g_WoT + (size_t)(n0 + r1) * INNER + k0 + kc1);
        CP_COMMIT();
    }
    for (int s = 0; s < NS; s++) {
        int buf = s & 1;
        CP_WAIT(1);
        __syncthreads();
        const float* As = smA[buf];
        const float* Bs = smB[buf];
        #pragma unroll
        for (int ks = 0; ks < 2; ks++) {
            int kb = ks * 8;
            uint32_t af[4][4], bf[4][2];
            #pragma unroll
            for (int mi = 0; mi < 4; mi++) {
                int rr = wm + mi * 16 + grp;
                af[mi][0] = f2tf(As[rr * SMSTRIDE + kb + tg]);
                af[mi][1] = f2tf(As[(rr + 8) * SMSTRIDE + kb + tg]);
                af[mi][2] = f2tf(As[rr * SMSTRIDE + kb + tg + 4]);
                af[mi][3] = f2tf(As[(rr + 8) * SMSTRIDE + kb + tg + 4]);
            }
            #pragma unroll
            for (int ni = 0; ni < 4; ni++) {
                int cc = wn + ni * 8 + grp;
                bf[ni][0] = f2tf(Bs[cc * SMSTRIDE + kb + tg]);
                bf[ni][1] = f2tf(Bs[cc * SMSTRIDE + kb + tg + 4]);
            }
            #pragma unroll
            for (int mi = 0; mi < 4; mi++)
                #pragma unroll
                for (int ni = 0; ni < 4; ni++)
                    mma_tf32(acc[mi][ni], af[mi], bf[ni]);
        }
        __syncthreads();
        if (s + 2 < NS) {
            int k0 = (s + 2) * 16;
            uint32_t ao = (uint32_t)(buf * 128 * SMSTRIDE * 4);
            CP16(bA + ao + (r0 * SMSTRIDE + kc0) * 4, g_gate + (size_t)(m0 + r0) * INNER + k0 + kc0);
            CP16(bA + ao + (r1 * SMSTRIDE + kc1) * 4, g_gate + (size_t)(m0 + r1) * INNER + k0 + kc1);
            CP16(bB + ao + (r0 * SMSTRIDE + kc0) * 4, g_WoT + (size_t)(n0 + r0) * INNER + k0 + kc0);
            CP16(bB + ao + (r1 * SMSTRIDE + kc1) * 4, g_WoT + (size_t)(n0 + r1) * INNER + k0 + kc1);
        }
        CP_COMMIT();
    }
    #pragma unroll
    for (int mi = 0; mi < 4; mi++) {
        int rr = m0 + wm + mi * 16 + grp;
        float ys0 = g_ysc[rr], ys1 = g_ysc[rr + 8];
        #pragma unroll
        for (int ni = 0; ni < 4; ni++) {
            int cc = n0 + wn + ni * 8 + 2 * tg;
            float2 x0 = *(const float2*)&x[(size_t)rr * 512 + cc];
            float2 x1 = *(const float2*)&x[(size_t)(rr + 8) * 512 + cc];
            float2 lo = {x0.x + ys0 * acc[mi][ni][0], x0.y + ys0 * acc[mi][ni][1]};
            float2 hi = {x1.x + ys1 * acc[mi][ni][2], x1.y + ys1 * acc[mi][ni][3]};
            *(float2*)&out[(size_t)rr * 512 + cc] = lo;
            *(float2*)&out[(size_t)(rr + 8) * 512 + cc] = hi;
        }
    }
}

// ---------------- launch ----------------
extern "C" void kernel_launch(void* const* d_in, const int* in_sizes, int n_in,
                              void* d_out, int out_size) {
    const float* x  = (const float*)d_in[0];
    const float* nw = (const float*)d_in[1];
    const float* nb = (const float*)d_in[2];
    const float* Wi = (const float*)d_in[3];
    const float* cw = (const float*)d_in[4];
    const float* A  = (const float*)d_in[5];
    const float* Bm = (const float*)d_in[6];
    const float* Cm = (const float*)d_in[7];
    const float* Wo = (const float*)d_in[8];
    float* out = (float*)d_out;

    float* WiT; cudaGetSymbolAddress((void**)&WiT, g_WiT);
    float* WoT; cudaGetSymbolAddress((void**)&WoT, g_WoT);

    ln_kernel<<<NROWS, 128>>>(x, nw, nb);
    transpose_kernel<<<dim3(72, 16), 256>>>(Wi, WiT, 512, 2304);
    transpose_kernel<<<dim3(16, 24), 256>>>(Wo, WoT, 768, 512);
    gemm1_mma<<<dim3(18, 128), 256>>>();
    conv_kernel<<<NROWS, 256>>>(cw);
    scan2_kernel<<<BSZ, 32>>>(Bm, A);
    ysc_kernel<<<NROWS / 8, 256>>>(Cm);
    gemm2_mma<<<dim3(4, 128), 256>>>(x, out);
}

// round 5
// speedup vs baseline: 5.4048x; 1.2927x over previous
#include <cuda_runtime.h>
#include <math.h>
#include <stdint.h>

#define D_MODEL 512
#define INNER   768
#define NSTATE  64
#define LSEQ    2048
#define BSZ     8
#define NROWS   (BSZ * LSEQ)      // 16384
#define PROJC   (3 * INNER)       // 2304
#define NCHUNK  64                // chunks per batch
#define CLEN    32                // timesteps per chunk
#define NBC     (BSZ * NCHUNK)    // 512
#define MSTR    68                // row stride of g_M (65 used, padded)

// ---------------- scratch ----------------
__device__ float g_h[(size_t)NROWS * D_MODEL];
__device__ float g_proj[(size_t)NROWS * PROJC];
__device__ float g_gate[(size_t)NROWS * INNER];
__device__ float g_WiT[(size_t)PROJC * D_MODEL];
__device__ float g_WoT[(size_t)D_MODEL * INNER];
__device__ float g_S[NROWS + 8];
__device__ float g_dt[NROWS + 8];
__device__ float g_M[(size_t)(NBC + 1) * NSTATE * MSTR];   // +1 chunk pad for prefetch
__device__ float g_sinit[(size_t)NBC * NSTATE];
__device__ float g_ysc[NROWS];

// ---------------- helpers ----------------
__device__ __forceinline__ uint32_t smem_u32(const void* p) {
    uint32_t a;
    asm("{ .reg .u64 t; cvta.to.shared.u64 t, %1; cvt.u32.u64 %0, t; }" : "=r"(a) : "l"(p));
    return a;
}
#define CP16(dst, src) \
    asm volatile("cp.async.cg.shared.global [%0], [%1], 16;" :: "r"(dst), "l"(src))
#define CP_COMMIT() asm volatile("cp.async.commit_group;" ::: "memory")
#define CP_WAIT(n)  asm volatile("cp.async.wait_group %0;" :: "n"(n) : "memory")

__device__ __forceinline__ void mma_tf32(float* d, const uint32_t* a, const uint32_t* b) {
    asm volatile("mma.sync.aligned.m16n8k8.row.col.f32.tf32.tf32.f32 "
                 "{%0,%1,%2,%3}, {%4,%5,%6,%7}, {%8,%9}, {%0,%1,%2,%3};"
                 : "+f"(d[0]), "+f"(d[1]), "+f"(d[2]), "+f"(d[3])
                 : "r"(a[0]), "r"(a[1]), "r"(a[2]), "r"(a[3]), "r"(b[0]), "r"(b[1]));
}
#define F2T(x) __float_as_uint(x)   // mma tf32 uses bits [31:13]; truncation is fine

#define SMSTRIDE 20

// ---------------- transpose ----------------
__global__ __launch_bounds__(256) void transpose_kernel(const float* __restrict__ src,
                                                        float* __restrict__ dst,
                                                        int R, int C) {
    __shared__ float tile[32][33];
    int c0 = blockIdx.x * 32, r0 = blockIdx.y * 32;
    int x = threadIdx.x & 31, y = threadIdx.x >> 5;
    #pragma unroll
    for (int j = 0; j < 32; j += 8) tile[y + j][x] = src[(size_t)(r0 + y + j) * C + c0 + x];
    __syncthreads();
    #pragma unroll
    for (int j = 0; j < 32; j += 8) dst[(size_t)(c0 + y + j) * R + r0 + x] = tile[x][y + j];
}

// ---------------- LayerNorm ----------------
__global__ __launch_bounds__(128) void ln_kernel(const float* __restrict__ x,
                                                 const float* __restrict__ w,
                                                 const float* __restrict__ b) {
    int row = blockIdx.x, tid = threadIdx.x;
    const float4* xr = (const float4*)(x + (size_t)row * D_MODEL);
    float4 v = xr[tid];
    float s  = v.x + v.y + v.z + v.w;
    float ss = v.x*v.x + v.y*v.y + v.z*v.z + v.w*v.w;
    for (int o = 16; o; o >>= 1) {
        s  += __shfl_xor_sync(0xffffffffu, s, o);
        ss += __shfl_xor_sync(0xffffffffu, ss, o);
    }
    __shared__ float rs[4], rss[4];
    int wid = tid >> 5, lane = tid & 31;
    if (lane == 0) { rs[wid] = s; rss[wid] = ss; }
    __syncthreads();
    s  = rs[0] + rs[1] + rs[2] + rs[3];
    ss = rss[0] + rss[1] + rss[2] + rss[3];
    float mu = s * (1.0f / 512.0f);
    float rstd = rsqrtf(ss * (1.0f / 512.0f) - mu * mu + 1e-5f);
    float4 wv = ((const float4*)w)[tid];
    float4 bv = ((const float4*)b)[tid];
    float4 o;
    o.x = (v.x - mu) * rstd * wv.x + bv.x;
    o.y = (v.y - mu) * rstd * wv.y + bv.y;
    o.z = (v.z - mu) * rstd * wv.z + bv.z;
    o.w = (v.w - mu) * rstd * wv.w + bv.w;
    ((float4*)(g_h + (size_t)row * D_MODEL))[tid] = o;
}

// ---------------- GEMM1: g_proj = g_h @ WiT^T ----------------
__global__ __launch_bounds__(256, 2) void gemm1_mma() {
    __shared__ float smA[2][128 * SMSTRIDE];
    __shared__ float smB[2][128 * SMSTRIDE];
    int tid = threadIdx.x, wid = tid >> 5, lane = tid & 31;
    int m0 = blockIdx.y * 128, n0 = blockIdx.x * 128;
    int wm = (wid >> 2) * 64, wn = (wid & 3) * 32;
    int grp = lane >> 2, tg = lane & 3;
    uint32_t bA = smem_u32(smA), bB = smem_u32(smB);

    int r0 = tid >> 2, kc0 = (tid & 3) * 4;
    int r1 = (tid + 256) >> 2, kc1 = ((tid + 256) & 3) * 4;
    const int NS = 32;

    float acc[4][4][4] = {};

    #pragma unroll 1
    for (int s = 0; s < 2; s++) {
        int k0 = s * 16;
        uint32_t ao = (uint32_t)(s * 128 * SMSTRIDE * 4);
        CP16(bA + ao + (r0 * SMSTRIDE + kc0) * 4, g_h + (size_t)(m0 + r0) * 512 + k0 + kc0);
        CP16(bA + ao + (r1 * SMSTRIDE + kc1) * 4, g_h + (size_t)(m0 + r1) * 512 + k0 + kc1);
        CP16(bB + ao + (r0 * SMSTRIDE + kc0) * 4, g_WiT + (size_t)(n0 + r0) * 512 + k0 + kc0);
        CP16(bB + ao + (r1 * SMSTRIDE + kc1) * 4, g_WiT + (size_t)(n0 + r1) * 512 + k0 + kc1);
        CP_COMMIT();
    }
    for (int s = 0; s < NS; s++) {
        int buf = s & 1;
        CP_WAIT(1);
        __syncthreads();
        const float* As = smA[buf];
        const float* Bs = smB[buf];
        #pragma unroll
        for (int ks = 0; ks < 2; ks++) {
            int kb = ks * 8;
            uint32_t af[4][4], bf[4][2];
            #pragma unroll
            for (int mi = 0; mi < 4; mi++) {
                int rr = wm + mi * 16 + grp;
                af[mi][0] = F2T(As[rr * SMSTRIDE + kb + tg]);
                af[mi][1] = F2T(As[(rr + 8) * SMSTRIDE + kb + tg]);
                af[mi][2] = F2T(As[rr * SMSTRIDE + kb + tg + 4]);
                af[mi][3] = F2T(As[(rr + 8) * SMSTRIDE + kb + tg + 4]);
            }
            #pragma unroll
            for (int ni = 0; ni < 4; ni++) {
                int cc = wn + ni * 8 + grp;
                bf[ni][0] = F2T(Bs[cc * SMSTRIDE + kb + tg]);
                bf[ni][1] = F2T(Bs[cc * SMSTRIDE + kb + tg + 4]);
            }
            #pragma unroll
            for (int mi = 0; mi < 4; mi++)
                #pragma unroll
                for (int ni = 0; ni < 4; ni++)
                    mma_tf32(acc[mi][ni], af[mi], bf[ni]);
        }
        __syncthreads();
        if (s + 2 < NS) {
            int k0 = (s + 2) * 16;
            uint32_t ao = (uint32_t)(buf * 128 * SMSTRIDE * 4);
            CP16(bA + ao + (r0 * SMSTRIDE + kc0) * 4, g_h + (size_t)(m0 + r0) * 512 + k0 + kc0);
            CP16(bA + ao + (r1 * SMSTRIDE + kc1) * 4, g_h + (size_t)(m0 + r1) * 512 + k0 + kc1);
            CP16(bB + ao + (r0 * SMSTRIDE + kc0) * 4, g_WiT + (size_t)(n0 + r0) * 512 + k0 + kc0);
            CP16(bB + ao + (r1 * SMSTRIDE + kc1) * 4, g_WiT + (size_t)(n0 + r1) * 512 + k0 + kc1);
        }
        CP_COMMIT();
    }
    #pragma unroll
    for (int mi = 0; mi < 4; mi++)
        #pragma unroll
        for (int ni = 0; ni < 4; ni++) {
            int rr = m0 + wm + mi * 16 + grp;
            int cc = n0 + wn + ni * 8 + 2 * tg;
            float2 lo = {acc[mi][ni][0], acc[mi][ni][1]};
            float2 hi = {acc[mi][ni][2], acc[mi][ni][3]};
            *(float2*)&g_proj[(size_t)rr * PROJC + cc] = lo;
            *(float2*)&g_proj[(size_t)(rr + 8) * PROJC + cc] = hi;
        }
}

// ---------------- conv + silu + softplus-mean + gate sigmoid ----------------
__global__ __launch_bounds__(256) void conv_kernel(const float* __restrict__ cw) {
    int row = blockIdx.x, tid = threadIdx.x;
    int t = row & (LSEQ - 1);
    const float* pr = g_proj + (size_t)row * PROJC;
    float* gt = g_gate + (size_t)row * INNER;
    float sumU = 0.f, sumD = 0.f;
    #pragma unroll
    for (int j = 0; j < 3; j++) {
        int c = tid + j * 256;
        float d2 = pr[c];
        float d1 = (t >= 1) ? pr[(ptrdiff_t)c - PROJC] : 0.f;
        float d0 = (t >= 2) ? pr[(ptrdiff_t)c - 2 * PROJC] : 0.f;
        float z = cw[c*3] * d0 + cw[c*3+1] * d1 + cw[c*3+2] * d2;
        sumU += z / (1.f + expf(-z));
        float dr = pr[1536 + c];
        sumD += (dr > 20.f) ? dr : log1pf(expf(dr));
        float gv = pr[768 + c];
        gt[c] = 1.f / (1.f + expf(-gv));
    }
    for (int o = 16; o; o >>= 1) {
        sumU += __shfl_xor_sync(0xffffffffu, sumU, o);
        sumD += __shfl_xor_sync(0xffffffffu, sumD, o);
    }
    __shared__ float r1[8], r2[8];
    if ((tid & 31) == 0) { r1[tid >> 5] = sumU; r2[tid >> 5] = sumD; }
    __syncthreads();
    if (tid == 0) {
        float a = 0.f, d = 0.f;
        #pragma unroll
        for (int w = 0; w < 8; w++) { a += r1[w]; d += r2[w]; }
        g_S[row]  = a;
        g_dt[row] = fminf(d * (1.f / 768.f) + 1e-4f, 3.f);
    }
}

// ---------------- Phase A: per (batch,chunk) chunk transition (65 columns) ----------------
// Column c<64: homogeneous basis e_c (inputs off). Column 64: zero state, inputs on.
// Output (transposed): g_M[(bc*64 + i)*MSTR + c] = final state_i.
__global__ __launch_bounds__(128) void scanA_kernel(const float* __restrict__ Bm,
                                                    const float* __restrict__ A) {
    int bc = blockIdx.x;
    int w = threadIdx.x >> 5, l = threadIdx.x & 31;
    int c_raw = blockIdx.y * 4 + w;          // 0..67
    int c = c_raw > 64 ? 64 : c_raw;
    int i0 = 2 * l, i1 = 2 * l + 1;
    float e0 =  sqrtf(-A[i0 * 64 + i0]);
    float e1 = -sqrtf(-A[i1 * 64 + i1]);
    float e0sq = e0 * e0, e1sq = e1 * e1;
    float bv0 = Bm[(size_t)i0 * INNER], bv1 = Bm[(size_t)i1 * INNER];
    bool inp = (c == 64);
    float s0 = (!inp && i0 == c) ? 1.f : 0.f;
    float s1 = (!inp && i1 == c) ? 1.f : 0.f;

    __shared__ float sdt[CLEN], sS[CLEN];
    size_t tbase = (size_t)bc * CLEN;
    if (threadIdx.x < CLEN) sdt[threadIdx.x] = g_dt[tbase + threadIdx.x];
    else if (threadIdx.x < 2 * CLEN) sS[threadIdx.x - CLEN] = g_S[tbase + threadIdx.x - CLEN];
    __syncthreads();

    for (int t = 0; t < CLEN; t++) {
        float dt = sdt[t];
        float dtS = inp ? dt * sS[t] : 0.f;
        float invd0 = __fdividef(1.f, fmaf(dt, e0sq, 1.f));
        float invd1 = __fdividef(1.f, fmaf(dt, e1sq, 1.f));
        float k0 = e0 * invd0, k1 = e1 * invd1;
        float m0 = dt * k0,    m1 = dt * k1;
        float r0 = fmaf(dtS, bv0, s0);
        float r1 = fmaf(dtS, bv1, s1);
        float Bc = fmaf(invd1, k0 * r0, k1 * r1);
        float Ac = invd0 * invd1;
        #pragma unroll
        for (int ofs = 1; ofs < 32; ofs <<= 1) {
            float Au = __shfl_up_sync(0xffffffffu, Ac, ofs);
            float Bu = __shfl_up_sync(0xffffffffu, Bc, ofs);
            if (l >= ofs) { Bc = fmaf(Ac, Bu, Bc); Ac *= Au; }
        }
        float pex = __shfl_up_sync(0xffffffffu, Bc, 1);
        if (l == 0) pex = 0.f;
        float x0 = fmaf(-m0, pex, invd0 * r0);
        float p0 = fmaf(invd0, pex, k0 * r0);
        float x1 = fmaf(-m1, p0, invd1 * r1);
        s0 = x0; s1 = x1;
    }
    if (c_raw <= 64) {
        float* dst = g_M + (size_t)bc * NSTATE * MSTR;
        dst[(size_t)i0 * MSTR + c] = s0;
        dst[(size_t)i1 * MSTR + c] = s1;
    }
}

// ---------------- Phase B: per batch, serial affine combine over 64 chunks ----------------
__global__ __launch_bounds__(256) void scanB_kernel() {
    int b = blockIdx.x, tid = threadIdx.x;
    int i = tid >> 2, p = tid & 3;
    __shared__ __align__(16) float ss[64];
    if (tid < 64) ss[tid] = 0.f;
    __syncthreads();
    const float* rowp = g_M + ((size_t)(b * NCHUNK) * NSTATE + i) * MSTR;
    const size_t cstep = (size_t)NSTATE * MSTR;
    float4 m[4]; float vv;
    #pragma unroll
    for (int q = 0; q < 4; q++) m[q] = *(const float4*)(rowp + p * 16 + q * 4);
    vv = rowp[64];
    for (int k = 0; k < NCHUNK; k++) {
        if (p == 0) g_sinit[(size_t)(b * NCHUNK + k) * NSTATE + i] = ss[i];
        float4 mn[4]; float vn;
        const float* np = rowp + (size_t)(k + 1) * cstep;
        #pragma unroll
        for (int q = 0; q < 4; q++) mn[q] = *(const float4*)(np + p * 16 + q * 4);
        vn = np[64];
        float part = 0.f;
        #pragma unroll
        for (int q = 0; q < 4; q++) {
            float4 sv = *(const float4*)(ss + p * 16 + q * 4);
            part += m[q].x * sv.x + m[q].y * sv.y + m[q].z * sv.z + m[q].w * sv.w;
        }
        part += __shfl_xor_sync(0xffffffffu, part, 1);
        part += __shfl_xor_sync(0xffffffffu, part, 2);
        __syncthreads();
        if (p == 0) ss[i] = part + vv;
        __syncthreads();
        #pragma unroll
        for (int q = 0; q < 4; q++) m[q] = mn[q];
        vv = vn;
    }
}

// ---------------- Phase C: per (batch,chunk) replay 32 steps, emit ysc ----------------
__global__ __launch_bounds__(32) void scanC_kernel(const float* __restrict__ Bm,
                                                   const float* __restrict__ Cm,
                                                   const float* __restrict__ A) {
    int bc = blockIdx.x, l = threadIdx.x;
    int i0 = 2 * l, i1 = 2 * l + 1;
    float e0 =  sqrtf(-A[i0 * 64 + i0]);
    float e1 = -sqrtf(-A[i1 * 64 + i1]);
    float e0sq = e0 * e0, e1sq = e1 * e1;
    float bv0 = Bm[(size_t)i0 * INNER], bv1 = Bm[(size_t)i1 * INNER];
    float C0 = Cm[i0], C1 = Cm[i1];
    float s0 = g_sinit[(size_t)bc * NSTATE + i0];
    float s1 = g_sinit[(size_t)bc * NSTATE + i1];
    __shared__ float sdt[CLEN], sS[CLEN];
    size_t tbase = (size_t)bc * CLEN;
    sdt[l] = g_dt[tbase + l];
    sS[l]  = g_S[tbase + l];
    __syncwarp();
    for (int t = 0; t < CLEN; t++) {
        float dt = sdt[t], S = sS[t];
        float invd0 = __fdividef(1.f, fmaf(dt, e0sq, 1.f));
        float invd1 = __fdividef(1.f, fmaf(dt, e1sq, 1.f));
        float k0 = e0 * invd0, k1 = e1 * invd1;
        float m0 = dt * k0,    m1 = dt * k1;
        float dtS = dt * S;
        float r0 = fmaf(dtS, bv0, s0);
        float r1 = fmaf(dtS, bv1, s1);
        float Bc = fmaf(invd1, k0 * r0, k1 * r1);
        float Ac = invd0 * invd1;
        #pragma unroll
        for (int ofs = 1; ofs < 32; ofs <<= 1) {
            float Au = __shfl_up_sync(0xffffffffu, Ac, ofs);
            float Bu = __shfl_up_sync(0xffffffffu, Bc, ofs);
            if (l >= ofs) { Bc = fmaf(Ac, Bu, Bc); Ac *= Au; }
        }
        float pex = __shfl_up_sync(0xffffffffu, Bc, 1);
        if (l == 0) pex = 0.f;
        float x0 = fmaf(-m0, pex, invd0 * r0);
        float p0 = fmaf(invd0, pex, k0 * r0);
        float x1 = fmaf(-m1, p0, invd1 * r1);
        s0 = x0; s1 = x1;
        float wv = C0 * x0 + C1 * x1;
        #pragma unroll
        for (int o = 16; o; o >>= 1) wv += __shfl_xor_sync(0xffffffffu, wv, o);
        if (l == 0) g_ysc[tbase + t] = wv;
    }
}

// ---------------- GEMM2: out = x + ysc * (g_gate @ WoT^T) ----------------
__global__ __launch_bounds__(256, 2) void gemm2_mma(const float* __restrict__ x,
                                                    float* __restrict__ out) {
    __shared__ float smA[2][128 * SMSTRIDE];
    __shared__ float smB[2][128 * SMSTRIDE];
    int tid = threadIdx.x, wid = tid >> 5, lane = tid & 31;
    int m0 = blockIdx.y * 128, n0 = blockIdx.x * 128;
    int wm = (wid >> 2) * 64, wn = (wid & 3) * 32;
    int grp = lane >> 2, tg = lane & 3;
    uint32_t bA = smem_u32(smA), bB = smem_u32(smB);

    int r0 = tid >> 2, kc0 = (tid & 3) * 4;
    int r1 = (tid + 256) >> 2, kc1 = ((tid + 256) & 3) * 4;
    const int NS = 48;

    float acc[4][4][4] = {};

    #pragma unroll 1
    for (int s = 0; s < 2; s++) {
        int k0 = s * 16;
        uint32_t ao = (uint32_t)(s * 128 * SMSTRIDE * 4);
        CP16(bA + ao + (r0 * SMSTRIDE + kc0) * 4, g_gate + (size_t)(m0 + r0) * INNER + k0 + kc0);
        CP16(bA + ao + (r1 * SMSTRIDE + kc1) * 4, g_gate + (size_t)(m0 + r1) * INNER + k0 + kc1);
        CP16(bB + ao + (r0 * SMSTRIDE + kc0) * 4, g_WoT + (size_t)(n0 + r0) * INNER + k0 + kc0);
        CP16(bB + ao + (r1 * SMSTRIDE + kc1) * 4, g_WoT + (size_t)(n0 + r1) * INNER + k0 + kc1);
        CP_COMMIT();
    }
    for (int s = 0; s < NS; s++) {
        int buf = s & 1;
        CP_WAIT(1);
        __syncthreads();
        const float* As = smA[buf];
        const float* Bs = smB[buf];
        #pragma unroll
        for (int ks = 0; ks < 2; ks++) {
            int kb = ks * 8;
            uint32_t af[4][4], bf[4][2];
            #pragma unroll
            for (int mi = 0; mi < 4; mi++) {
                int rr = wm + mi * 16 + grp;
                af[mi][0] = F2T(As[rr * SMSTRIDE + kb + tg]);
                af[mi][1] = F2T(As[(rr + 8) * SMSTRIDE + kb + tg]);
                af[mi][2] = F2T(As[rr * SMSTRIDE + kb + tg + 4]);
                af[mi][3] = F2T(As[(rr + 8) * SMSTRIDE + kb + tg + 4]);
            }
            #pragma unroll
            for (int ni = 0; ni < 4; ni++) {
                int cc = wn + ni * 8 + grp;
                bf[ni][0] = F2T(Bs[cc * SMSTRIDE + kb + tg]);
                bf[ni][1] = F2T(Bs[cc * SMSTRIDE + kb + tg + 4]);
            }
            #pragma unroll
            for (int mi = 0; mi < 4; mi++)
                #pragma unroll
                for (int ni = 0; ni < 4; ni++)
                    mma_tf32(acc[mi][ni], af[mi], bf[ni]);
        }
        __syncthreads();
        if (s + 2 < NS) {
            int k0 = (s + 2) * 16;
            uint32_t ao = (uint32_t)(buf * 128 * SMSTRIDE * 4);
            CP16(bA + ao + (r0 * SMSTRIDE + kc0) * 4, g_gate + (size_t)(m0 + r0) * INNER + k0 + kc0);
            CP16(bA + ao + (r1 * SMSTRIDE + kc1) * 4, g_gate + (size_t)(m0 + r1) * INNER + k0 + kc1);
            CP16(bB + ao + (r0 * SMSTRIDE + kc0) * 4, g_WoT + (size_t)(n0 + r0) * INNER + k0 + kc0);
            CP16(bB + ao + (r1 * SMSTRIDE + kc1) * 4, g_WoT + (size_t)(n0 + r1) * INNER + k0 + kc1);
        }
        CP_COMMIT();
    }
    #pragma unroll
    for (int mi = 0; mi < 4; mi++) {
        int rr = m0 + wm + mi * 16 + grp;
        float ys0 = g_ysc[rr], ys1 = g_ysc[rr + 8];
        #pragma unroll
        for (int ni = 0; ni < 4; ni++) {
            int cc = n0 + wn + ni * 8 + 2 * tg;
            float2 x0 = *(const float2*)&x[(size_t)rr * 512 + cc];
            float2 x1 = *(const float2*)&x[(size_t)(rr + 8) * 512 + cc];
            float2 lo = {x0.x + ys0 * acc[mi][ni][0], x0.y + ys0 * acc[mi][ni][1]};
            float2 hi = {x1.x + ys1 * acc[mi][ni][2], x1.y + ys1 * acc[mi][ni][3]};
            *(float2*)&out[(size_t)rr * 512 + cc] = lo;
            *(float2*)&out[(size_t)(rr + 8) * 512 + cc] = hi;
        }
    }
}

// ---------------- launch ----------------
extern "C" void kernel_launch(void* const* d_in, const int* in_sizes, int n_in,
                              void* d_out, int out_size) {
    const float* x  = (const float*)d_in[0];
    const float* nw = (const float*)d_in[1];
    const float* nb = (const float*)d_in[2];
    const float* Wi = (const float*)d_in[3];
    const float* cw = (const float*)d_in[4];
    const float* A  = (const float*)d_in[5];
    const float* Bm = (const float*)d_in[6];
    const float* Cm = (const float*)d_in[7];
    const float* Wo = (const float*)d_in[8];
    float* out = (float*)d_out;

    float* WiT; cudaGetSymbolAddress((void**)&WiT, g_WiT);
    float* WoT; cudaGetSymbolAddress((void**)&WoT, g_WoT);

    ln_kernel<<<NROWS, 128>>>(x, nw, nb);
    transpose_kernel<<<dim3(72, 16), 256>>>(Wi, WiT, 512, 2304);
    transpose_kernel<<<dim3(16, 24), 256>>>(Wo, WoT, 768, 512);
    gemm1_mma<<<dim3(18, 128), 256>>>();
    conv_kernel<<<NROWS, 256>>>(cw);
    scanA_kernel<<<dim3(NBC, 17), 128>>>(Bm, A);
    scanB_kernel<<<BSZ, 256>>>();
    scanC_kernel<<<NBC, 32>>>(Bm, Cm, A);
    gemm2_mma<<<dim3(4, 128), 256>>>(x, out);
}

// round 6
// speedup vs baseline: 5.5621x; 1.0291x over previous
#include <cuda_runtime.h>
#include <math.h>
#include <stdint.h>

#define D_MODEL 512
#define INNER   768
#define NSTATE  64
#define LSEQ    2048
#define BSZ     8
#define NROWS   (BSZ * LSEQ)      // 16384
#define PROJC   (3 * INNER)       // 2304
#define NCHUNK  64
#define CLEN    32
#define NBC     (BSZ * NCHUNK)    // 512
#define MSTR    68

// ---------------- scratch ----------------
__device__ float g_h[(size_t)NROWS * D_MODEL];
__device__ float g_proj[(size_t)NROWS * PROJC];
__device__ float g_gate[(size_t)NROWS * INNER];
__device__ float g_WiT[(size_t)PROJC * D_MODEL];
__device__ float g_WoT[(size_t)D_MODEL * INNER];
__device__ float g_S[NROWS + 8];
__device__ float g_dt[NROWS + 8];
__device__ float g_M[(size_t)(NBC + 1) * NSTATE * MSTR];
__device__ float g_sinit[(size_t)NBC * NSTATE];
__device__ float g_ysc[NROWS];

// ---------------- helpers ----------------
__device__ __forceinline__ uint32_t smem_u32(const void* p) {
    uint32_t a;
    asm("{ .reg .u64 t; cvta.to.shared.u64 t, %1; cvt.u32.u64 %0, t; }" : "=r"(a) : "l"(p));
    return a;
}
#define CP16(dst, src) \
    asm volatile("cp.async.cg.shared.global [%0], [%1], 16;" :: "r"(dst), "l"(src))
#define CP_COMMIT() asm volatile("cp.async.commit_group;" ::: "memory")
#define CP_WAIT(n)  asm volatile("cp.async.wait_group %0;" :: "n"(n) : "memory")

__device__ __forceinline__ void mma_tf32(float* d, const uint32_t* a, const uint32_t* b) {
    asm volatile("mma.sync.aligned.m16n8k8.row.col.f32.tf32.tf32.f32 "
                 "{%0,%1,%2,%3}, {%4,%5,%6,%7}, {%8,%9}, {%0,%1,%2,%3};"
                 : "+f"(d[0]), "+f"(d[1]), "+f"(d[2]), "+f"(d[3])
                 : "r"(a[0]), "r"(a[1]), "r"(a[2]), "r"(a[3]), "r"(b[0]), "r"(b[1]));
}
#define F2T(x) __float_as_uint(x)

#define SMSTRIDE 20
#define STAGES   4
#define STG_ELEMS (128 * SMSTRIDE)              // floats per operand per stage
#define GEMM_SMEM (STAGES * STG_ELEMS * 2 * 4)  // bytes

// ---------------- transpose ----------------
__global__ __launch_bounds__(256) void transpose_kernel(const float* __restrict__ src,
                                                        float* __restrict__ dst,
                                                        int R, int C) {
    __shared__ float tile[32][33];
    int c0 = blockIdx.x * 32, r0 = blockIdx.y * 32;
    int x = threadIdx.x & 31, y = threadIdx.x >> 5;
    #pragma unroll
    for (int j = 0; j < 32; j += 8) tile[y + j][x] = src[(size_t)(r0 + y + j) * C + c0 + x];
    __syncthreads();
    #pragma unroll
    for (int j = 0; j < 32; j += 8) dst[(size_t)(c0 + y + j) * R + r0 + x] = tile[x][y + j];
}

// ---------------- LayerNorm ----------------
__global__ __launch_bounds__(128) void ln_kernel(const float* __restrict__ x,
                                                 const float* __restrict__ w,
                                                 const float* __restrict__ b) {
    int row = blockIdx.x, tid = threadIdx.x;
    const float4* xr = (const float4*)(x + (size_t)row * D_MODEL);
    float4 v = xr[tid];
    float s  = v.x + v.y + v.z + v.w;
    float ss = v.x*v.x + v.y*v.y + v.z*v.z + v.w*v.w;
    for (int o = 16; o; o >>= 1) {
        s  += __shfl_xor_sync(0xffffffffu, s, o);
        ss += __shfl_xor_sync(0xffffffffu, ss, o);
    }
    __shared__ float rs[4], rss[4];
    int wid = tid >> 5, lane = tid & 31;
    if (lane == 0) { rs[wid] = s; rss[wid] = ss; }
    __syncthreads();
    s  = rs[0] + rs[1] + rs[2] + rs[3];
    ss = rss[0] + rss[1] + rss[2] + rss[3];
    float mu = s * (1.0f / 512.0f);
    float rstd = rsqrtf(ss * (1.0f / 512.0f) - mu * mu + 1e-5f);
    float4 wv = ((const float4*)w)[tid];
    float4 bv = ((const float4*)b)[tid];
    float4 o;
    o.x = (v.x - mu) * rstd * wv.x + bv.x;
    o.y = (v.y - mu) * rstd * wv.y + bv.y;
    o.z = (v.z - mu) * rstd * wv.z + bv.z;
    o.w = (v.w - mu) * rstd * wv.w + bv.w;
    ((float4*)(g_h + (size_t)row * D_MODEL))[tid] = o;
}

// ---------------- GEMM core (4-stage cp.async ring, tf32 mma.sync) ----------------
// A: [M][lda] row-major from gA, B: [N][lda] row-major from gB (both K-major).
template <int NS>
__device__ __forceinline__ void gemm_body(const float* __restrict__ gA, size_t lda,
                                          const float* __restrict__ gB, size_t ldb,
                                          int m0, int n0, float acc[4][4][4]) {
    extern __shared__ __align__(16) float dsm[];
    float* smA = dsm;
    float* smB = dsm + STAGES * STG_ELEMS;
    int tid = threadIdx.x, wid = tid >> 5, lane = tid & 31;
    int wm = (wid >> 2) * 64, wn = (wid & 3) * 32;
    int grp = lane >> 2, tg = lane & 3;
    uint32_t bA = smem_u32(smA), bB = smem_u32(smB);

    int r0 = tid >> 2, kc0 = (tid & 3) * 4;
    int r1 = (tid + 256) >> 2, kc1 = ((tid + 256) & 3) * 4;

    #pragma unroll
    for (int s = 0; s < STAGES - 1; s++) {
        int k0 = s * 16;
        uint32_t ao = (uint32_t)(s * STG_ELEMS * 4);
        CP16(bA + ao + (r0 * SMSTRIDE + kc0) * 4, gA + (size_t)(m0 + r0) * lda + k0 + kc0);
        CP16(bA + ao + (r1 * SMSTRIDE + kc1) * 4, gA + (size_t)(m0 + r1) * lda + k0 + kc1);
        CP16(bB + ao + (r0 * SMSTRIDE + kc0) * 4, gB + (size_t)(n0 + r0) * ldb + k0 + kc0);
        CP16(bB + ao + (r1 * SMSTRIDE + kc1) * 4, gB + (size_t)(n0 + r1) * ldb + k0 + kc1);
        CP_COMMIT();
    }
    for (int s = 0; s < NS; s++) {
        int buf = s & (STAGES - 1);
        CP_WAIT(STAGES - 2);
        __syncthreads();
        const float* As = smA + buf * STG_ELEMS;
        const float* Bs = smB + buf * STG_ELEMS;
        #pragma unroll
        for (int ks = 0; ks < 2; ks++) {
            int kb = ks * 8;
            uint32_t af[4][4], bf[4][2];
            #pragma unroll
            for (int mi = 0; mi < 4; mi++) {
                int rr = wm + mi * 16 + grp;
                af[mi][0] = F2T(As[rr * SMSTRIDE + kb + tg]);
                af[mi][1] = F2T(As[(rr + 8) * SMSTRIDE + kb + tg]);
                af[mi][2] = F2T(As[rr * SMSTRIDE + kb + tg + 4]);
                af[mi][3] = F2T(As[(rr + 8) * SMSTRIDE + kb + tg + 4]);
            }
            #pragma unroll
            for (int ni = 0; ni < 4; ni++) {
                int cc = wn + ni * 8 + grp;
                bf[ni][0] = F2T(Bs[cc * SMSTRIDE + kb + tg]);
                bf[ni][1] = F2T(Bs[cc * SMSTRIDE + kb + tg + 4]);
            }
            #pragma unroll
            for (int mi = 0; mi < 4; mi++)
                #pragma unroll
                for (int ni = 0; ni < 4; ni++)
                    mma_tf32(acc[mi][ni], af[mi], bf[ni]);
        }
        if (s + STAGES - 1 < NS) {
            int k0 = (s + STAGES - 1) * 16;
            uint32_t ao = (uint32_t)(((s + STAGES - 1) & (STAGES - 1)) * STG_ELEMS * 4);
            CP16(bA + ao + (r0 * SMSTRIDE + kc0) * 4, gA + (size_t)(m0 + r0) * lda + k0 + kc0);
            CP16(bA + ao + (r1 * SMSTRIDE + kc1) * 4, gA + (size_t)(m0 + r1) * lda + k0 + kc1);
            CP16(bB + ao + (r0 * SMSTRIDE + kc0) * 4, gB + (size_t)(n0 + r0) * ldb + k0 + kc0);
            CP16(bB + ao + (r1 * SMSTRIDE + kc1) * 4, gB + (size_t)(n0 + r1) * ldb + k0 + kc1);
        }
        CP_COMMIT();
    }
}

// ---------------- GEMM1: g_proj = g_h @ WiT^T ----------------
__global__ __launch_bounds__(256, 2) void gemm1_mma() {
    int tid = threadIdx.x, wid = tid >> 5, lane = tid & 31;
    int m0 = blockIdx.y * 128, n0 = blockIdx.x * 128;
    int wm = (wid >> 2) * 64, wn = (wid & 3) * 32;
    int grp = lane >> 2, tg = lane & 3;
    float acc[4][4][4] = {};
    gemm_body<32>(g_h, 512, g_WiT, 512, m0, n0, acc);
    #pragma unroll
    for (int mi = 0; mi < 4; mi++)
        #pragma unroll
        for (int ni = 0; ni < 4; ni++) {
            int rr = m0 + wm + mi * 16 + grp;
            int cc = n0 + wn + ni * 8 + 2 * tg;
            float2 lo = {acc[mi][ni][0], acc[mi][ni][1]};
            float2 hi = {acc[mi][ni][2], acc[mi][ni][3]};
            *(float2*)&g_proj[(size_t)rr * PROJC + cc] = lo;
            *(float2*)&g_proj[(size_t)(rr + 8) * PROJC + cc] = hi;
        }
}

// ---------------- conv + silu + softplus-mean + gate sigmoid ----------------
__global__ __launch_bounds__(256) void conv_kernel(const float* __restrict__ cw) {
    int row = blockIdx.x, tid = threadIdx.x;
    int t = row & (LSEQ - 1);
    const float* pr = g_proj + (size_t)row * PROJC;
    float* gt = g_gate + (size_t)row * INNER;
    float sumU = 0.f, sumD = 0.f;
    #pragma unroll
    for (int j = 0; j < 3; j++) {
        int c = tid + j * 256;
        float d2 = pr[c];
        float d1 = (t >= 1) ? pr[(ptrdiff_t)c - PROJC] : 0.f;
        float d0 = (t >= 2) ? pr[(ptrdiff_t)c - 2 * PROJC] : 0.f;
        float z = cw[c*3] * d0 + cw[c*3+1] * d1 + cw[c*3+2] * d2;
        sumU += z / (1.f + expf(-z));
        float dr = pr[1536 + c];
        sumD += (dr > 20.f) ? dr : log1pf(expf(dr));
        float gv = pr[768 + c];
        gt[c] = 1.f / (1.f + expf(-gv));
    }
    for (int o = 16; o; o >>= 1) {
        sumU += __shfl_xor_sync(0xffffffffu, sumU, o);
        sumD += __shfl_xor_sync(0xffffffffu, sumD, o);
    }
    __shared__ float r1[8], r2[8];
    if ((tid & 31) == 0) { r1[tid >> 5] = sumU; r2[tid >> 5] = sumD; }
    __syncthreads();
    if (tid == 0) {
        float a = 0.f, d = 0.f;
        #pragma unroll
        for (int w = 0; w < 8; w++) { a += r1[w]; d += r2[w]; }
        g_S[row]  = a;
        g_dt[row] = fminf(d * (1.f / 768.f) + 1e-4f, 3.f);
    }
}

// ---------------- Phase A ----------------
__global__ __launch_bounds__(128) void scanA_kernel(const float* __restrict__ Bm,
                                                    const float* __restrict__ A) {
    int bc = blockIdx.x;
    int w = threadIdx.x >> 5, l = threadIdx.x & 31;
    int c_raw = blockIdx.y * 4 + w;
    int c = c_raw > 64 ? 64 : c_raw;
    int i0 = 2 * l, i1 = 2 * l + 1;
    float e0 =  sqrtf(-A[i0 * 64 + i0]);
    float e1 = -sqrtf(-A[i1 * 64 + i1]);
    float e0sq = e0 * e0, e1sq = e1 * e1;
    float bv0 = Bm[(size_t)i0 * INNER], bv1 = Bm[(size_t)i1 * INNER];
    bool inp = (c == 64);
    float s0 = (!inp && i0 == c) ? 1.f : 0.f;
    float s1 = (!inp && i1 == c) ? 1.f : 0.f;

    __shared__ float sdt[CLEN], sS[CLEN];
    size_t tbase = (size_t)bc * CLEN;
    if (threadIdx.x < CLEN) sdt[threadIdx.x] = g_dt[tbase + threadIdx.x];
    else if (threadIdx.x < 2 * CLEN) sS[threadIdx.x - CLEN] = g_S[tbase + threadIdx.x - CLEN];
    __syncthreads();

    for (int t = 0; t < CLEN; t++) {
        float dt = sdt[t];
        float dtS = inp ? dt * sS[t] : 0.f;
        float invd0 = __fdividef(1.f, fmaf(dt, e0sq, 1.f));
        float invd1 = __fdividef(1.f, fmaf(dt, e1sq, 1.f));
        float k0 = e0 * invd0, k1 = e1 * invd1;
        float m0 = dt * k0,    m1 = dt * k1;
        float r0 = fmaf(dtS, bv0, s0);
        float r1 = fmaf(dtS, bv1, s1);
        float Bc = fmaf(invd1, k0 * r0, k1 * r1);
        float Ac = invd0 * invd1;
        #pragma unroll
        for (int ofs = 1; ofs < 32; ofs <<= 1) {
            float Au = __shfl_up_sync(0xffffffffu, Ac, ofs);
            float Bu = __shfl_up_sync(0xffffffffu, Bc, ofs);
            if (l >= ofs) { Bc = fmaf(Ac, Bu, Bc); Ac *= Au; }
        }
        float pex = __shfl_up_sync(0xffffffffu, Bc, 1);
        if (l == 0) pex = 0.f;
        float x0 = fmaf(-m0, pex, invd0 * r0);
        float p0 = fmaf(invd0, pex, k0 * r0);
        float x1 = fmaf(-m1, p0, invd1 * r1);
        s0 = x0; s1 = x1;
    }
    if (c_raw <= 64) {
        float* dst = g_M + (size_t)bc * NSTATE * MSTR;
        dst[(size_t)i0 * MSTR + c] = s0;
        dst[(size_t)i1 * MSTR + c] = s1;
    }
}

// ---------------- Phase B ----------------
__global__ __launch_bounds__(256) void scanB_kernel() {
    int b = blockIdx.x, tid = threadIdx.x;
    int i = tid >> 2, p = tid & 3;
    __shared__ __align__(16) float ss[64];
    if (tid < 64) ss[tid] = 0.f;
    __syncthreads();
    const float* rowp = g_M + ((size_t)(b * NCHUNK) * NSTATE + i) * MSTR;
    const size_t cstep = (size_t)NSTATE * MSTR;
    float4 m[4]; float vv;
    #pragma unroll
    for (int q = 0; q < 4; q++) m[q] = *(const float4*)(rowp + p * 16 + q * 4);
    vv = rowp[64];
    for (int k = 0; k < NCHUNK; k++) {
        if (p == 0) g_sinit[(size_t)(b * NCHUNK + k) * NSTATE + i] = ss[i];
        float4 mn[4]; float vn;
        const float* np = rowp + (size_t)(k + 1) * cstep;
        #pragma unroll
        for (int q = 0; q < 4; q++) mn[q] = *(const float4*)(np + p * 16 + q * 4);
        vn = np[64];
        float part = 0.f;
        #pragma unroll
        for (int q = 0; q < 4; q++) {
            float4 sv = *(const float4*)(ss + p * 16 + q * 4);
            part += m[q].x * sv.x + m[q].y * sv.y + m[q].z * sv.z + m[q].w * sv.w;
        }
        part += __shfl_xor_sync(0xffffffffu, part, 1);
        part += __shfl_xor_sync(0xffffffffu, part, 2);
        __syncthreads();
        if (p == 0) ss[i] = part + vv;
        __syncthreads();
        #pragma unroll
        for (int q = 0; q < 4; q++) m[q] = mn[q];
        vv = vn;
    }
}

// ---------------- Phase C ----------------
__global__ __launch_bounds__(32) void scanC_kernel(const float* __restrict__ Bm,
                                                   const float* __restrict__ Cm,
                                                   const float* __restrict__ A) {
    int bc = blockIdx.x, l = threadIdx.x;
    int i0 = 2 * l, i1 = 2 * l + 1;
    float e0 =  sqrtf(-A[i0 * 64 + i0]);
    float e1 = -sqrtf(-A[i1 * 64 + i1]);
    float e0sq = e0 * e0, e1sq = e1 * e1;
    float bv0 = Bm[(size_t)i0 * INNER], bv1 = Bm[(size_t)i1 * INNER];
    float C0 = Cm[i0], C1 = Cm[i1];
    float s0 = g_sinit[(size_t)bc * NSTATE + i0];
    float s1 = g_sinit[(size_t)bc * NSTATE + i1];
    __shared__ float sdt[CLEN], sS[CLEN];
    size_t tbase = (size_t)bc * CLEN;
    sdt[l] = g_dt[tbase + l];
    sS[l]  = g_S[tbase + l];
    __syncwarp();
    for (int t = 0; t < CLEN; t++) {
        float dt = sdt[t], S = sS[t];
        float invd0 = __fdividef(1.f, fmaf(dt, e0sq, 1.f));
        float invd1 = __fdividef(1.f, fmaf(dt, e1sq, 1.f));
        float k0 = e0 * invd0, k1 = e1 * invd1;
        float m0 = dt * k0,    m1 = dt * k1;
        float dtS = dt * S;
        float r0 = fmaf(dtS, bv0, s0);
        float r1 = fmaf(dtS, bv1, s1);
        float Bc = fmaf(invd1, k0 * r0, k1 * r1);
        float Ac = invd0 * invd1;
        #pragma unroll
        for (int ofs = 1; ofs < 32; ofs <<= 1) {
            float Au = __shfl_up_sync(0xffffffffu, Ac, ofs);
            float Bu = __shfl_up_sync(0xffffffffu, Bc, ofs);
            if (l >= ofs) { Bc = fmaf(Ac, Bu, Bc); Ac *= Au; }
        }
        float pex = __shfl_up_sync(0xffffffffu, Bc, 1);
        if (l == 0) pex = 0.f;
        float x0 = fmaf(-m0, pex, invd0 * r0);
        float p0 = fmaf(invd0, pex, k0 * r0);
        float x1 = fmaf(-m1, p0, invd1 * r1);
        s0 = x0; s1 = x1;
        float wv = C0 * x0 + C1 * x1;
        #pragma unroll
        for (int o = 16; o; o >>= 1) wv += __shfl_xor_sync(0xffffffffu, wv, o);
        if (l == 0) g_ysc[tbase + t] = wv;
    }
}

// ---------------- GEMM2: out = x + ysc * (g_gate @ WoT^T) ----------------
__global__ __launch_bounds__(256, 2) void gemm2_mma(const float* __restrict__ x,
                                                    float* __restrict__ out) {
    int tid = threadIdx.x, wid = tid >> 5, lane = tid & 31;
    int m0 = blockIdx.y * 128, n0 = blockIdx.x * 128;
    int wm = (wid >> 2) * 64, wn = (wid & 3) * 32;
    int grp = lane >> 2, tg = lane & 3;
    float acc[4][4][4] = {};
    gemm_body<48>(g_gate, INNER, g_WoT, INNER, m0, n0, acc);
    #pragma unroll
    for (int mi = 0; mi < 4; mi++) {
        int rr = m0 + wm + mi * 16 + grp;
        float ys0 = g_ysc[rr], ys1 = g_ysc[rr + 8];
        #pragma unroll
        for (int ni = 0; ni < 4; ni++) {
            int cc = n0 + wn + ni * 8 + 2 * tg;
            float2 x0 = *(const float2*)&x[(size_t)rr * 512 + cc];
            float2 x1 = *(const float2*)&x[(size_t)(rr + 8) * 512 + cc];
            float2 lo = {x0.x + ys0 * acc[mi][ni][0], x0.y + ys0 * acc[mi][ni][1]};
            float2 hi = {x1.x + ys1 * acc[mi][ni][2], x1.y + ys1 * acc[mi][ni][3]};
            *(float2*)&out[(size_t)rr * 512 + cc] = lo;
            *(float2*)&out[(size_t)(rr + 8) * 512 + cc] = hi;
        }
    }
}

// ---------------- launch ----------------
extern "C" void kernel_launch(void* const* d_in, const int* in_sizes, int n_in,
                              void* d_out, int out_size) {
    const float* x  = (const float*)d_in[0];
    const float* nw = (const float*)d_in[1];
    const float* nb = (const float*)d_in[2];
    const float* Wi = (const float*)d_in[3];
    const float* cw = (const float*)d_in[4];
    const float* A  = (const float*)d_in[5];
    const float* Bm = (const float*)d_in[6];
    const float* Cm = (const float*)d_in[7];
    const float* Wo = (const float*)d_in[8];
    float* out = (float*)d_out;

    cudaFuncSetAttribute(gemm1_mma, cudaFuncAttributeMaxDynamicSharedMemorySize, GEMM_SMEM);
    cudaFuncSetAttribute(gemm2_mma, cudaFuncAttributeMaxDynamicSharedMemorySize, GEMM_SMEM);

    float* WiT; cudaGetSymbolAddress((void**)&WiT, g_WiT);
    float* WoT; cudaGetSymbolAddress((void**)&WoT, g_WoT);

    ln_kernel<<<NROWS, 128>>>(x, nw, nb);
    transpose_kernel<<<dim3(72, 16), 256>>>(Wi, WiT, 512, 2304);
    transpose_kernel<<<dim3(16, 24), 256>>>(Wo, WoT, 768, 512);
    gemm1_mma<<<dim3(18, 128), 256, GEMM_SMEM>>>();
    conv_kernel<<<NROWS, 256>>>(cw);
    scanA_kernel<<<dim3(NBC, 17), 128>>>(Bm, A);
    scanB_kernel<<<BSZ, 256>>>();
    scanC_kernel<<<NBC, 32>>>(Bm, Cm, A);
    gemm2_mma<<<dim3(4, 128), 256, GEMM_SMEM>>>(x, out);
}

// round 7
// speedup vs baseline: 7.7637x; 1.3958x over previous
#include <cuda_runtime.h>
#include <cuda_fp16.h>
#include <math.h>
#include <stdint.h>

#define D_MODEL 512
#define INNER   768
#define NSTATE  64
#define LSEQ    2048
#define BSZ     8
#define NROWS   (BSZ * LSEQ)      // 16384
#define PROJC   (3 * INNER)       // 2304
#define NCHUNK  64
#define CLEN    32
#define NBC     (BSZ * NCHUNK)    // 512
#define MSTR    68

// ---------------- scratch ----------------
__device__ __half g_h[(size_t)NROWS * D_MODEL];
__device__ float  g_proj[(size_t)NROWS * PROJC];
__device__ __half g_gate[(size_t)NROWS * INNER];
__device__ __half g_WiT[(size_t)PROJC * D_MODEL];
__device__ __half g_WoT[(size_t)D_MODEL * INNER];
__device__ float  g_S[NROWS + 8];
__device__ float  g_dt[NROWS + 8];
__device__ float  g_M[(size_t)(NBC + 1) * NSTATE * MSTR];
__device__ float  g_sinit[(size_t)NBC * NSTATE];
__device__ float  g_ysc[NROWS];

// ---------------- helpers ----------------
__device__ __forceinline__ uint32_t smem_u32(const void* p) {
    uint32_t a;
    asm("{ .reg .u64 t; cvta.to.shared.u64 t, %1; cvt.u32.u64 %0, t; }" : "=r"(a) : "l"(p));
    return a;
}
#define CP16(dst, src) \
    asm volatile("cp.async.cg.shared.global [%0], [%1], 16;" :: "r"(dst), "l"(src))
#define CP_COMMIT() asm volatile("cp.async.commit_group;" ::: "memory")
#define CP_WAIT(n)  asm volatile("cp.async.wait_group %0;" :: "n"(n) : "memory")

__device__ __forceinline__ void mma_f16(float* d, const uint32_t* a, const uint32_t* b) {
    asm volatile("mma.sync.aligned.m16n8k16.row.col.f32.f16.f16.f32 "
                 "{%0,%1,%2,%3}, {%4,%5,%6,%7}, {%8,%9}, {%0,%1,%2,%3};"
                 : "+f"(d[0]), "+f"(d[1]), "+f"(d[2]), "+f"(d[3])
                 : "r"(a[0]), "r"(a[1]), "r"(a[2]), "r"(a[3]), "r"(b[0]), "r"(b[1]));
}

#define HSTR     40                              // halfs per smem row (32 + 8 pad)
#define STAGES   4
#define STG_H    (128 * HSTR)                    // halfs per operand per stage
#define GEMM_SMEM (STAGES * STG_H * 2 * 2)       // bytes

// ---------------- transpose + fp16 convert: dst[C][R] = (half)src[R][C] ----------------
__global__ __launch_bounds__(256) void transpose_kernel(const float* __restrict__ src,
                                                        __half* __restrict__ dst,
                                                        int R, int C) {
    __shared__ float tile[32][33];
    int c0 = blockIdx.x * 32, r0 = blockIdx.y * 32;
    int x = threadIdx.x & 31, y = threadIdx.x >> 5;
    #pragma unroll
    for (int j = 0; j < 32; j += 8) tile[y + j][x] = src[(size_t)(r0 + y + j) * C + c0 + x];
    __syncthreads();
    #pragma unroll
    for (int j = 0; j < 32; j += 8)
        dst[(size_t)(c0 + y + j) * R + r0 + x] = __float2half_rn(tile[x][y + j]);
}

// ---------------- LayerNorm -> fp16 ----------------
__global__ __launch_bounds__(128) void ln_kernel(const float* __restrict__ x,
                                                 const float* __restrict__ w,
                                                 const float* __restrict__ b) {
    int row = blockIdx.x, tid = threadIdx.x;
    const float4* xr = (const float4*)(x + (size_t)row * D_MODEL);
    float4 v = xr[tid];
    float s  = v.x + v.y + v.z + v.w;
    float ss = v.x*v.x + v.y*v.y + v.z*v.z + v.w*v.w;
    for (int o = 16; o; o >>= 1) {
        s  += __shfl_xor_sync(0xffffffffu, s, o);
        ss += __shfl_xor_sync(0xffffffffu, ss, o);
    }
    __shared__ float rs[4], rss[4];
    int wid = tid >> 5, lane = tid & 31;
    if (lane == 0) { rs[wid] = s; rss[wid] = ss; }
    __syncthreads();
    s  = rs[0] + rs[1] + rs[2] + rs[3];
    ss = rss[0] + rss[1] + rss[2] + rss[3];
    float mu = s * (1.0f / 512.0f);
    float rstd = rsqrtf(ss * (1.0f / 512.0f) - mu * mu + 1e-5f);
    float4 wv = ((const float4*)w)[tid];
    float4 bv = ((const float4*)b)[tid];
    __half2 h0 = __floats2half2_rn((v.x - mu) * rstd * wv.x + bv.x,
                                   (v.y - mu) * rstd * wv.y + bv.y);
    __half2 h1 = __floats2half2_rn((v.z - mu) * rstd * wv.z + bv.z,
                                   (v.w - mu) * rstd * wv.w + bv.w);
    uint2 pk = {*(uint32_t*)&h0, *(uint32_t*)&h1};
    *(uint2*)(g_h + (size_t)row * D_MODEL + tid * 4) = pk;
}

// ---------------- GEMM core (fp16 m16n8k16, 4-stage cp.async ring) ----------------
// gA: [M][lda] halfs row-major (K-major), gB: [N][ldb] halfs row-major.
template <int NS>
__device__ __forceinline__ void gemm_body(const __half* __restrict__ gA, size_t lda,
                                          const __half* __restrict__ gB, size_t ldb,
                                          int m0, int n0, float acc[4][4][4]) {
    extern __shared__ __align__(16) __half dsm[];
    __half* smA = dsm;
    __half* smB = dsm + STAGES * STG_H;
    int tid = threadIdx.x, wid = tid >> 5, lane = tid & 31;
    int wm = (wid >> 2) * 64, wn = (wid & 3) * 32;
    int grp = lane >> 2, tg = lane & 3;
    uint32_t bA = smem_u32(smA), bB = smem_u32(smB);

    // stage copy: 128 rows x 32 halfs; 16B chunk = 8 halfs; 4 chunks/row; 512 chunks.
    int r0 = tid >> 2, kc0 = (tid & 3) * 8;
    int r1 = (tid + 256) >> 2, kc1 = ((tid + 256) & 3) * 8;

    #pragma unroll
    for (int s = 0; s < STAGES - 1; s++) {
        int k0 = s * 32;
        uint32_t ao = (uint32_t)(s * STG_H * 2);
        CP16(bA + ao + (r0 * HSTR + kc0) * 2, gA + (size_t)(m0 + r0) * lda + k0 + kc0);
        CP16(bA + ao + (r1 * HSTR + kc1) * 2, gA + (size_t)(m0 + r1) * lda + k0 + kc1);
        CP16(bB + ao + (r0 * HSTR + kc0) * 2, gB + (size_t)(n0 + r0) * ldb + k0 + kc0);
        CP16(bB + ao + (r1 * HSTR + kc1) * 2, gB + (size_t)(n0 + r1) * ldb + k0 + kc1);
        CP_COMMIT();
    }
    for (int s = 0; s < NS; s++) {
        int buf = s & (STAGES - 1);
        CP_WAIT(STAGES - 2);
        __syncthreads();
        const __half* As = smA + buf * STG_H;
        const __half* Bs = smB + buf * STG_H;
        #pragma unroll
        for (int ks = 0; ks < 2; ks++) {
            int kb = ks * 16;
            uint32_t af[4][4], bf[4][2];
            #pragma unroll
            for (int mi = 0; mi < 4; mi++) {
                int rr = wm + mi * 16 + grp;
                af[mi][0] = *(const uint32_t*)&As[rr * HSTR + kb + 2 * tg];
                af[mi][1] = *(const uint32_t*)&As[(rr + 8) * HSTR + kb + 2 * tg];
                af[mi][2] = *(const uint32_t*)&As[rr * HSTR + kb + 2 * tg + 8];
                af[mi][3] = *(const uint32_t*)&As[(rr + 8) * HSTR + kb + 2 * tg + 8];
            }
            #pragma unroll
            for (int ni = 0; ni < 4; ni++) {
                int cc = wn + ni * 8 + grp;
                bf[ni][0] = *(const uint32_t*)&Bs[cc * HSTR + kb + 2 * tg];
                bf[ni][1] = *(const uint32_t*)&Bs[cc * HSTR + kb + 2 * tg + 8];
            }
            #pragma unroll
            for (int mi = 0; mi < 4; mi++)
                #pragma unroll
                for (int ni = 0; ni < 4; ni++)
                    mma_f16(acc[mi][ni], af[mi], bf[ni]);
        }
        if (s + STAGES - 1 < NS) {
            int k0 = (s + STAGES - 1) * 32;
            uint32_t ao = (uint32_t)(((s + STAGES - 1) & (STAGES - 1)) * STG_H * 2);
            CP16(bA + ao + (r0 * HSTR + kc0) * 2, gA + (size_t)(m0 + r0) * lda + k0 + kc0);
            CP16(bA + ao + (r1 * HSTR + kc1) * 2, gA + (size_t)(m0 + r1) * lda + k0 + kc1);
            CP16(bB + ao + (r0 * HSTR + kc0) * 2, gB + (size_t)(n0 + r0) * ldb + k0 + kc0);
            CP16(bB + ao + (r1 * HSTR + kc1) * 2, gB + (size_t)(n0 + r1) * ldb + k0 + kc1);
        }
        CP_COMMIT();
    }
}

// ---------------- GEMM1: g_proj = g_h @ WiT^T ----------------
__global__ __launch_bounds__(256, 2) void gemm1_mma() {
    int tid = threadIdx.x, wid = tid >> 5, lane = tid & 31;
    int m0 = blockIdx.y * 128, n0 = blockIdx.x * 128;
    int wm = (wid >> 2) * 64, wn = (wid & 3) * 32;
    int grp = lane >> 2, tg = lane & 3;
    float acc[4][4][4] = {};
    gemm_body<16>(g_h, 512, g_WiT, 512, m0, n0, acc);
    #pragma unroll
    for (int mi = 0; mi < 4; mi++)
        #pragma unroll
        for (int ni = 0; ni < 4; ni++) {
            int rr = m0 + wm + mi * 16 + grp;
            int cc = n0 + wn + ni * 8 + 2 * tg;
            float2 lo = {acc[mi][ni][0], acc[mi][ni][1]};
            float2 hi = {acc[mi][ni][2], acc[mi][ni][3]};
            *(float2*)&g_proj[(size_t)rr * PROJC + cc] = lo;
            *(float2*)&g_proj[(size_t)(rr + 8) * PROJC + cc] = hi;
        }
}

// ---------------- conv + silu + softplus-mean + gate sigmoid(fp16) ----------------
__global__ __launch_bounds__(256) void conv_kernel(const float* __restrict__ cw) {
    int row = blockIdx.x, tid = threadIdx.x;
    int t = row & (LSEQ - 1);
    const float* pr = g_proj + (size_t)row * PROJC;
    __half* gt = g_gate + (size_t)row * INNER;
    float sumU = 0.f, sumD = 0.f;
    #pragma unroll
    for (int j = 0; j < 3; j++) {
        int c = tid + j * 256;
        float d2 = pr[c];
        float d1 = (t >= 1) ? pr[(ptrdiff_t)c - PROJC] : 0.f;
        float d0 = (t >= 2) ? pr[(ptrdiff_t)c - 2 * PROJC] : 0.f;
        float z = cw[c*3] * d0 + cw[c*3+1] * d1 + cw[c*3+2] * d2;
        sumU += z / (1.f + expf(-z));
        float dr = pr[1536 + c];
        sumD += (dr > 20.f) ? dr : log1pf(expf(dr));
        float gv = pr[768 + c];
        gt[c] = __float2half_rn(1.f / (1.f + expf(-gv)));
    }
    for (int o = 16; o; o >>= 1) {
        sumU += __shfl_xor_sync(0xffffffffu, sumU, o);
        sumD += __shfl_xor_sync(0xffffffffu, sumD, o);
    }
    __shared__ float r1[8], r2[8];
    if ((tid & 31) == 0) { r1[tid >> 5] = sumU; r2[tid >> 5] = sumD; }
    __syncthreads();
    if (tid == 0) {
        float a = 0.f, d = 0.f;
        #pragma unroll
        for (int w = 0; w < 8; w++) { a += r1[w]; d += r2[w]; }
        g_S[row]  = a;
        g_dt[row] = fminf(d * (1.f / 768.f) + 1e-4f, 3.f);
    }
}

// ---------------- Phase A ----------------
__global__ __launch_bounds__(128) void scanA_kernel(const float* __restrict__ Bm,
                                                    const float* __restrict__ A) {
    int bc = blockIdx.x;
    int w = threadIdx.x >> 5, l = threadIdx.x & 31;
    int c_raw = blockIdx.y * 4 + w;
    int c = c_raw > 64 ? 64 : c_raw;
    int i0 = 2 * l, i1 = 2 * l + 1;
    float e0 =  sqrtf(-A[i0 * 64 + i0]);
    float e1 = -sqrtf(-A[i1 * 64 + i1]);
    float e0sq = e0 * e0, e1sq = e1 * e1;
    float bv0 = Bm[(size_t)i0 * INNER], bv1 = Bm[(size_t)i1 * INNER];
    bool inp = (c == 64);
    float s0 = (!inp && i0 == c) ? 1.f : 0.f;
    float s1 = (!inp && i1 == c) ? 1.f : 0.f;

    __shared__ float sdt[CLEN], sS[CLEN];
    size_t tbase = (size_t)bc * CLEN;
    if (threadIdx.x < CLEN) sdt[threadIdx.x] = g_dt[tbase + threadIdx.x];
    else if (threadIdx.x < 2 * CLEN) sS[threadIdx.x - CLEN] = g_S[tbase + threadIdx.x - CLEN];
    __syncthreads();

    for (int t = 0; t < CLEN; t++) {
        float dt = sdt[t];
        float dtS = inp ? dt * sS[t] : 0.f;
        float invd0 = __fdividef(1.f, fmaf(dt, e0sq, 1.f));
        float invd1 = __fdividef(1.f, fmaf(dt, e1sq, 1.f));
        float k0 = e0 * invd0, k1 = e1 * invd1;
        float m0 = dt * k0,    m1 = dt * k1;
        float r0 = fmaf(dtS, bv0, s0);
        float r1 = fmaf(dtS, bv1, s1);
        float Bc = fmaf(invd1, k0 * r0, k1 * r1);
        float Ac = invd0 * invd1;
        #pragma unroll
        for (int ofs = 1; ofs < 32; ofs <<= 1) {
            float Au = __shfl_up_sync(0xffffffffu, Ac, ofs);
            float Bu = __shfl_up_sync(0xffffffffu, Bc, ofs);
            if (l >= ofs) { Bc = fmaf(Ac, Bu, Bc); Ac *= Au; }
        }
        float pex = __shfl_up_sync(0xffffffffu, Bc, 1);
        if (l == 0) pex = 0.f;
        float x0 = fmaf(-m0, pex, invd0 * r0);
        float p0 = fmaf(invd0, pex, k0 * r0);
        float x1 = fmaf(-m1, p0, invd1 * r1);
        s0 = x0; s1 = x1;
    }
    if (c_raw <= 64) {
        float* dst = g_M + (size_t)bc * NSTATE * MSTR;
        dst[(size_t)i0 * MSTR + c] = s0;
        dst[(size_t)i1 * MSTR + c] = s1;
    }
}

// ---------------- Phase B ----------------
__global__ __launch_bounds__(256) void scanB_kernel() {
    int b = blockIdx.x, tid = threadIdx.x;
    int i = tid >> 2, p = tid & 3;
    __shared__ __align__(16) float ss[64];
    if (tid < 64) ss[tid] = 0.f;
    __syncthreads();
    const float* rowp = g_M + ((size_t)(b * NCHUNK) * NSTATE + i) * MSTR;
    const size_t cstep = (size_t)NSTATE * MSTR;
    float4 m[4]; float vv;
    #pragma unroll
    for (int q = 0; q < 4; q++) m[q] = *(const float4*)(rowp + p * 16 + q * 4);
    vv = rowp[64];
    for (int k = 0; k < NCHUNK; k++) {
        if (p == 0) g_sinit[(size_t)(b * NCHUNK + k) * NSTATE + i] = ss[i];
        float4 mn[4]; float vn;
        const float* np = rowp + (size_t)(k + 1) * cstep;
        #pragma unroll
        for (int q = 0; q < 4; q++) mn[q] = *(const float4*)(np + p * 16 + q * 4);
        vn = np[64];
        float part = 0.f;
        #pragma unroll
        for (int q = 0; q < 4; q++) {
            float4 sv = *(const float4*)(ss + p * 16 + q * 4);
            part += m[q].x * sv.x + m[q].y * sv.y + m[q].z * sv.z + m[q].w * sv.w;
        }
        part += __shfl_xor_sync(0xffffffffu, part, 1);
        part += __shfl_xor_sync(0xffffffffu, part, 2);
        __syncthreads();
        if (p == 0) ss[i] = part + vv;
        __syncthreads();
        #pragma unroll
        for (int q = 0; q < 4; q++) m[q] = mn[q];
        vv = vn;
    }
}

// ---------------- Phase C ----------------
__global__ __launch_bounds__(32) void scanC_kernel(const float* __restrict__ Bm,
                                                   const float* __restrict__ Cm,
                                                   const float* __restrict__ A) {
    int bc = blockIdx.x, l = threadIdx.x;
    int i0 = 2 * l, i1 = 2 * l + 1;
    float e0 =  sqrtf(-A[i0 * 64 + i0]);
    float e1 = -sqrtf(-A[i1 * 64 + i1]);
    float e0sq = e0 * e0, e1sq = e1 * e1;
    float bv0 = Bm[(size_t)i0 * INNER], bv1 = Bm[(size_t)i1 * INNER];
    float C0 = Cm[i0], C1 = Cm[i1];
    float s0 = g_sinit[(size_t)bc * NSTATE + i0];
    float s1 = g_sinit[(size_t)bc * NSTATE + i1];
    __shared__ float sdt[CLEN], sS[CLEN];
    size_t tbase = (size_t)bc * CLEN;
    sdt[l] = g_dt[tbase + l];
    sS[l]  = g_S[tbase + l];
    __syncwarp();
    for (int t = 0; t < CLEN; t++) {
        float dt = sdt[t], S = sS[t];
        float invd0 = __fdividef(1.f, fmaf(dt, e0sq, 1.f));
        float invd1 = __fdividef(1.f, fmaf(dt, e1sq, 1.f));
        float k0 = e0 * invd0, k1 = e1 * invd1;
        float m0 = dt * k0,    m1 = dt * k1;
        float dtS = dt * S;
        float r0 = fmaf(dtS, bv0, s0);
        float r1 = fmaf(dtS, bv1, s1);
        float Bc = fmaf(invd1, k0 * r0, k1 * r1);
        float Ac = invd0 * invd1;
        #pragma unroll
        for (int ofs = 1; ofs < 32; ofs <<= 1) {
            float Au = __shfl_up_sync(0xffffffffu, Ac, ofs);
            float Bu = __shfl_up_sync(0xffffffffu, Bc, ofs);
            if (l >= ofs) { Bc = fmaf(Ac, Bu, Bc); Ac *= Au; }
        }
        float pex = __shfl_up_sync(0xffffffffu, Bc, 1);
        if (l == 0) pex = 0.f;
        float x0 = fmaf(-m0, pex, invd0 * r0);
        float p0 = fmaf(invd0, pex, k0 * r0);
        float x1 = fmaf(-m1, p0, invd1 * r1);
        s0 = x0; s1 = x1;
        float wv = C0 * x0 + C1 * x1;
        #pragma unroll
        for (int o = 16; o; o >>= 1) wv += __shfl_xor_sync(0xffffffffu, wv, o);
        if (l == 0) g_ysc[tbase + t] = wv;
    }
}

// ---------------- GEMM2: out = x + ysc * (g_gate @ WoT^T) ----------------
__global__ __launch_bounds__(256, 2) void gemm2_mma(const float* __restrict__ x,
                                                    float* __restrict__ out) {
    int tid = threadIdx.x, wid = tid >> 5, lane = tid & 31;
    int m0 = blockIdx.y * 128, n0 = blockIdx.x * 128;
    int wm = (wid >> 2) * 64, wn = (wid & 3) * 32;
    int grp = lane >> 2, tg = lane & 3;
    float acc[4][4][4] = {};
    gemm_body<24>(g_gate, INNER, g_WoT, INNER, m0, n0, acc);
    #pragma unroll
    for (int mi = 0; mi < 4; mi++) {
        int rr = m0 + wm + mi * 16 + grp;
        float ys0 = g_ysc[rr], ys1 = g_ysc[rr + 8];
        #pragma unroll
        for (int ni = 0; ni < 4; ni++) {
            int cc = n0 + wn + ni * 8 + 2 * tg;
            float2 x0 = *(const float2*)&x[(size_t)rr * 512 + cc];
            float2 x1 = *(const float2*)&x[(size_t)(rr + 8) * 512 + cc];
            float2 lo = {x0.x + ys0 * acc[mi][ni][0], x0.y + ys0 * acc[mi][ni][1]};
            float2 hi = {x1.x + ys1 * acc[mi][ni][2], x1.y + ys1 * acc[mi][ni][3]};
            *(float2*)&out[(size_t)rr * 512 + cc] = lo;
            *(float2*)&out[(size_t)(rr + 8) * 512 + cc] = hi;
        }
    }
}

// ---------------- launch ----------------
extern "C" void kernel_launch(void* const* d_in, const int* in_sizes, int n_in,
                              void* d_out, int out_size) {
    const float* x  = (const float*)d_in[0];
    const float* nw = (const float*)d_in[1];
    const float* nb = (const float*)d_in[2];
    const float* Wi = (const float*)d_in[3];
    const float* cw = (const float*)d_in[4];
    const float* A  = (const float*)d_in[5];
    const float* Bm = (const float*)d_in[6];
    const float* Cm = (const float*)d_in[7];
    const float* Wo = (const float*)d_in[8];
    float* out = (float*)d_out;

    cudaFuncSetAttribute(gemm1_mma, cudaFuncAttributeMaxDynamicSharedMemorySize, GEMM_SMEM);
    cudaFuncSetAttribute(gemm2_mma, cudaFuncAttributeMaxDynamicSharedMemorySize, GEMM_SMEM);

    __half* WiT; cudaGetSymbolAddress((void**)&WiT, g_WiT);
    __half* WoT; cudaGetSymbolAddress((void**)&WoT, g_WoT);

    ln_kernel<<<NROWS, 128>>>(x, nw, nb);
    transpose_kernel<<<dim3(72, 16), 256>>>(Wi, WiT, 512, 2304);
    transpose_kernel<<<dim3(16, 24), 256>>>(Wo, WoT, 768, 512);
    gemm1_mma<<<dim3(18, 128), 256, GEMM_SMEM>>>();
    conv_kernel<<<NROWS, 256>>>(cw);
    scanA_kernel<<<dim3(NBC, 17), 128>>>(Bm, A);
    scanB_kernel<<<BSZ, 256>>>();
    scanC_kernel<<<NBC, 32>>>(Bm, Cm, A);
    gemm2_mma<<<dim3(4, 128), 256, GEMM_SMEM>>>(x, out);
}

// round 8
// speedup vs baseline: 8.3623x; 1.0771x over previous
#include <cuda_runtime.h>
#include <cuda_fp16.h>
#include <math.h>
#include <stdint.h>

#define D_MODEL 512
#define INNER   768
#define NSTATE  64
#define LSEQ    2048
#define BSZ     8
#define NROWS   (BSZ * LSEQ)      // 16384
#define PROJC   (3 * INNER)       // 2304
#define NCHUNK  64
#define CLEN    32
#define NBC     (BSZ * NCHUNK)    // 512
#define MSTR    68

// ---------------- scratch ----------------
__device__ __half g_h[(size_t)NROWS * D_MODEL];
__device__ __half g_proj[(size_t)NROWS * PROJC];
__device__ __half g_gate[(size_t)NROWS * INNER];
__device__ __half g_WiT[(size_t)PROJC * D_MODEL];
__device__ __half g_WoT[(size_t)D_MODEL * INNER];
__device__ float  g_S[NROWS + 8];
__device__ float  g_dt[NROWS + 8];
__device__ float  g_M[(size_t)(NBC + 1) * NSTATE * MSTR];
__device__ float  g_sinit[(size_t)NBC * NSTATE];
__device__ float  g_ysc[NROWS];

// ---------------- helpers ----------------
__device__ __forceinline__ uint32_t smem_u32(const void* p) {
    uint32_t a;
    asm("{ .reg .u64 t; cvta.to.shared.u64 t, %1; cvt.u32.u64 %0, t; }" : "=r"(a) : "l"(p));
    return a;
}
#define CP16(dst, src) \
    asm volatile("cp.async.cg.shared.global [%0], [%1], 16;" :: "r"(dst), "l"(src))
#define CP_COMMIT() asm volatile("cp.async.commit_group;" ::: "memory")
#define CP_WAIT(n)  asm volatile("cp.async.wait_group %0;" :: "n"(n) : "memory")
#define LDSM4(r0, r1, r2, r3, addr) \
    asm volatile("ldmatrix.sync.aligned.m8n8.x4.shared.b16 {%0,%1,%2,%3}, [%4];" \
                 : "=r"(r0), "=r"(r1), "=r"(r2), "=r"(r3) : "r"(addr))

__device__ __forceinline__ void mma_f16(float* d, const uint32_t* a, const uint32_t* b) {
    asm volatile("mma.sync.aligned.m16n8k16.row.col.f32.f16.f16.f32 "
                 "{%0,%1,%2,%3}, {%4,%5,%6,%7}, {%8,%9}, {%0,%1,%2,%3};"
                 : "+f"(d[0]), "+f"(d[1]), "+f"(d[2]), "+f"(d[3])
                 : "r"(a[0]), "r"(a[1]), "r"(a[2]), "r"(a[3]), "r"(b[0]), "r"(b[1]));
}

#define HSTR     40                              // halfs per smem row (32 + 8 pad)
#define STAGES   4
#define STG_H    (128 * HSTR)
#define GEMM_SMEM (STAGES * STG_H * 2 * 2)

// ---------------- transpose + fp16 convert ----------------
__global__ __launch_bounds__(256) void transpose_kernel(const float* __restrict__ src,
                                                        __half* __restrict__ dst,
                                                        int R, int C) {
    __shared__ float tile[32][33];
    int c0 = blockIdx.x * 32, r0 = blockIdx.y * 32;
    int x = threadIdx.x & 31, y = threadIdx.x >> 5;
    #pragma unroll
    for (int j = 0; j < 32; j += 8) tile[y + j][x] = src[(size_t)(r0 + y + j) * C + c0 + x];
    __syncthreads();
    #pragma unroll
    for (int j = 0; j < 32; j += 8)
        dst[(size_t)(c0 + y + j) * R + r0 + x] = __float2half_rn(tile[x][y + j]);
}

// ---------------- LayerNorm -> fp16 ----------------
__global__ __launch_bounds__(128) void ln_kernel(const float* __restrict__ x,
                                                 const float* __restrict__ w,
                                                 const float* __restrict__ b) {
    int row = blockIdx.x, tid = threadIdx.x;
    const float4* xr = (const float4*)(x + (size_t)row * D_MODEL);
    float4 v = xr[tid];
    float s  = v.x + v.y + v.z + v.w;
    float ss = v.x*v.x + v.y*v.y + v.z*v.z + v.w*v.w;
    for (int o = 16; o; o >>= 1) {
        s  += __shfl_xor_sync(0xffffffffu, s, o);
        ss += __shfl_xor_sync(0xffffffffu, ss, o);
    }
    __shared__ float rs[4], rss[4];
    int wid = tid >> 5, lane = tid & 31;
    if (lane == 0) { rs[wid] = s; rss[wid] = ss; }
    __syncthreads();
    s  = rs[0] + rs[1] + rs[2] + rs[3];
    ss = rss[0] + rss[1] + rss[2] + rss[3];
    float mu = s * (1.0f / 512.0f);
    float rstd = rsqrtf(ss * (1.0f / 512.0f) - mu * mu + 1e-5f);
    float4 wv = ((const float4*)w)[tid];
    float4 bv = ((const float4*)b)[tid];
    __half2 h0 = __floats2half2_rn((v.x - mu) * rstd * wv.x + bv.x,
                                   (v.y - mu) * rstd * wv.y + bv.y);
    __half2 h1 = __floats2half2_rn((v.z - mu) * rstd * wv.z + bv.z,
                                   (v.w - mu) * rstd * wv.w + bv.w);
    uint2 pk = {*(uint32_t*)&h0, *(uint32_t*)&h1};
    *(uint2*)(g_h + (size_t)row * D_MODEL + tid * 4) = pk;
}

// ---------------- GEMM core (fp16 m16n8k16, ldmatrix, 4-stage cp.async) ----------------
template <int NS>
__device__ __forceinline__ void gemm_body(const __half* __restrict__ gA, size_t lda,
                                          const __half* __restrict__ gB, size_t ldb,
                                          int m0, int n0, float acc[4][4][4]) {
    extern __shared__ __align__(16) __half dsm[];
    __half* smA = dsm;
    __half* smB = dsm + STAGES * STG_H;
    int tid = threadIdx.x, wid = tid >> 5, lane = tid & 31;
    int wm = (wid >> 2) * 64, wn = (wid & 3) * 32;
    uint32_t bA = smem_u32(smA), bB = smem_u32(smB);

    int r0 = tid >> 2, kc0 = (tid & 3) * 8;
    int r1 = (tid + 256) >> 2, kc1 = ((tid + 256) & 3) * 8;

    // ldmatrix lane-address components
    int aRow = wm + (lane & 15);            // + mi*16
    int aK   = (lane >> 4) * 8;             // + kb
    int bRow = wn + ((lane >> 4) << 3) + (lane & 7);   // + nb*16
    int bK   = ((lane >> 3) & 1) * 8;       // + kb

    #pragma unroll
    for (int s = 0; s < STAGES - 1; s++) {
        int k0 = s * 32;
        uint32_t ao = (uint32_t)(s * STG_H * 2);
        CP16(bA + ao + (r0 * HSTR + kc0) * 2, gA + (size_t)(m0 + r0) * lda + k0 + kc0);
        CP16(bA + ao + (r1 * HSTR + kc1) * 2, gA + (size_t)(m0 + r1) * lda + k0 + kc1);
        CP16(bB + ao + (r0 * HSTR + kc0) * 2, gB + (size_t)(n0 + r0) * ldb + k0 + kc0);
        CP16(bB + ao + (r1 * HSTR + kc1) * 2, gB + (size_t)(n0 + r1) * ldb + k0 + kc1);
        CP_COMMIT();
    }
    for (int s = 0; s < NS; s++) {
        int buf = s & (STAGES - 1);
        CP_WAIT(STAGES - 2);
        __syncthreads();
        uint32_t sA = bA + (uint32_t)(buf * STG_H * 2);
        uint32_t sB = bB + (uint32_t)(buf * STG_H * 2);
        #pragma unroll
        for (int ks = 0; ks < 2; ks++) {
            int kb = ks * 16;
            uint32_t af[4][4], bf[4][2];
            #pragma unroll
            for (int mi = 0; mi < 4; mi++) {
                uint32_t ad = sA + (uint32_t)(((aRow + mi * 16) * HSTR + kb + aK) * 2);
                LDSM4(af[mi][0], af[mi][1], af[mi][2], af[mi][3], ad);
            }
            #pragma unroll
            for (int nb = 0; nb < 2; nb++) {
                uint32_t bd = sB + (uint32_t)(((bRow + nb * 16) * HSTR + kb + bK) * 2);
                LDSM4(bf[2*nb][0], bf[2*nb][1], bf[2*nb+1][0], bf[2*nb+1][1], bd);
            }
            #pragma unroll
            for (int mi = 0; mi < 4; mi++)
                #pragma unroll
                for (int ni = 0; ni < 4; ni++)
                    mma_f16(acc[mi][ni], af[mi], bf[ni]);
        }
        if (s + STAGES - 1 < NS) {
            int k0 = (s + STAGES - 1) * 32;
            uint32_t ao = (uint32_t)(((s + STAGES - 1) & (STAGES - 1)) * STG_H * 2);
            CP16(bA + ao + (r0 * HSTR + kc0) * 2, gA + (size_t)(m0 + r0) * lda + k0 + kc0);
            CP16(bA + ao + (r1 * HSTR + kc1) * 2, gA + (size_t)(m0 + r1) * lda + k0 + kc1);
            CP16(bB + ao + (r0 * HSTR + kc0) * 2, gB + (size_t)(n0 + r0) * ldb + k0 + kc0);
            CP16(bB + ao + (r1 * HSTR + kc1) * 2, gB + (size_t)(n0 + r1) * ldb + k0 + kc1);
        }
        CP_COMMIT();
    }
}

// ---------------- GEMM1: g_proj(half) = g_h @ WiT^T ----------------
__global__ __launch_bounds__(256, 2) void gemm1_mma() {
    int tid = threadIdx.x, wid = tid >> 5, lane = tid & 31;
    int m0 = blockIdx.y * 128, n0 = blockIdx.x * 128;
    int wm = (wid >> 2) * 64, wn = (wid & 3) * 32;
    int grp = lane >> 2, tg = lane & 3;
    float acc[4][4][4] = {};
    gemm_body<16>(g_h, 512, g_WiT, 512, m0, n0, acc);
    #pragma unroll
    for (int mi = 0; mi < 4; mi++)
        #pragma unroll
        for (int ni = 0; ni < 4; ni++) {
            int rr = m0 + wm + mi * 16 + grp;
            int cc = n0 + wn + ni * 8 + 2 * tg;
            __half2 lo = __floats2half2_rn(acc[mi][ni][0], acc[mi][ni][1]);
            __half2 hi = __floats2half2_rn(acc[mi][ni][2], acc[mi][ni][3]);
            *(__half2*)&g_proj[(size_t)rr * PROJC + cc] = lo;
            *(__half2*)&g_proj[(size_t)(rr + 8) * PROJC + cc] = hi;
        }
}

// ---------------- conv + silu + softplus-mean + gate sigmoid ----------------
__global__ __launch_bounds__(256) void conv_kernel(const float* __restrict__ cw) {
    int row = blockIdx.x, tid = threadIdx.x;
    int t = row & (LSEQ - 1);
    const __half* pr = g_proj + (size_t)row * PROJC;
    __half* gt = g_gate + (size_t)row * INNER;
    float sumU = 0.f, sumD = 0.f;
    #pragma unroll
    for (int j = 0; j < 3; j++) {
        int c = tid + j * 256;
        float d2 = __half2float(pr[c]);
        float d1 = (t >= 1) ? __half2float(pr[(ptrdiff_t)c - PROJC]) : 0.f;
        float d0 = (t >= 2) ? __half2float(pr[(ptrdiff_t)c - 2 * PROJC]) : 0.f;
        float z = cw[c*3] * d0 + cw[c*3+1] * d1 + cw[c*3+2] * d2;
        sumU += z / (1.f + expf(-z));
        float dr = __half2float(pr[1536 + c]);
        sumD += (dr > 20.f) ? dr : log1pf(expf(dr));
        float gv = __half2float(pr[768 + c]);
        gt[c] = __float2half_rn(1.f / (1.f + expf(-gv)));
    }
    for (int o = 16; o; o >>= 1) {
        sumU += __shfl_xor_sync(0xffffffffu, sumU, o);
        sumD += __shfl_xor_sync(0xffffffffu, sumD, o);
    }
    __shared__ float r1[8], r2[8];
    if ((tid & 31) == 0) { r1[tid >> 5] = sumU; r2[tid >> 5] = sumD; }
    __syncthreads();
    if (tid == 0) {
        float a = 0.f, d = 0.f;
        #pragma unroll
        for (int w = 0; w < 8; w++) { a += r1[w]; d += r2[w]; }
        g_S[row]  = a;
        g_dt[row] = fminf(d * (1.f / 768.f) + 1e-4f, 3.f);
    }
}

// ---------------- Phase A ----------------
__global__ __launch_bounds__(128) void scanA_kernel(const float* __restrict__ Bm,
                                                    const float* __restrict__ A) {
    int bc = blockIdx.x;
    int w = threadIdx.x >> 5, l = threadIdx.x & 31;
    int c_raw = blockIdx.y * 4 + w;
    int c = c_raw > 64 ? 64 : c_raw;
    int i0 = 2 * l, i1 = 2 * l + 1;
    float e0 =  sqrtf(-A[i0 * 64 + i0]);
    float e1 = -sqrtf(-A[i1 * 64 + i1]);
    float e0sq = e0 * e0, e1sq = e1 * e1;
    float bv0 = Bm[(size_t)i0 * INNER], bv1 = Bm[(size_t)i1 * INNER];
    bool inp = (c == 64);
    float s0 = (!inp && i0 == c) ? 1.f : 0.f;
    float s1 = (!inp && i1 == c) ? 1.f : 0.f;

    __shared__ float sdt[CLEN], sS[CLEN];
    size_t tbase = (size_t)bc * CLEN;
    if (threadIdx.x < CLEN) sdt[threadIdx.x] = g_dt[tbase + threadIdx.x];
    else if (threadIdx.x < 2 * CLEN) sS[threadIdx.x - CLEN] = g_S[tbase + threadIdx.x - CLEN];
    __syncthreads();

    for (int t = 0; t < CLEN; t++) {
        float dt = sdt[t];
        float dtS = inp ? dt * sS[t] : 0.f;
        float invd0 = __fdividef(1.f, fmaf(dt, e0sq, 1.f));
        float invd1 = __fdividef(1.f, fmaf(dt, e1sq, 1.f));
        float k0 = e0 * invd0, k1 = e1 * invd1;
        float m0 = dt * k0,    m1 = dt * k1;
        float r0 = fmaf(dtS, bv0, s0);
        float r1 = fmaf(dtS, bv1, s1);
        float Bc = fmaf(invd1, k0 * r0, k1 * r1);
        float Ac = invd0 * invd1;
        #pragma unroll
        for (int ofs = 1; ofs < 32; ofs <<= 1) {
            float Au = __shfl_up_sync(0xffffffffu, Ac, ofs);
            float Bu = __shfl_up_sync(0xffffffffu, Bc, ofs);
            if (l >= ofs) { Bc = fmaf(Ac, Bu, Bc); Ac *= Au; }
        }
        float pex = __shfl_up_sync(0xffffffffu, Bc, 1);
        if (l == 0) pex = 0.f;
        float x0 = fmaf(-m0, pex, invd0 * r0);
        float p0 = fmaf(invd0, pex, k0 * r0);
        float x1 = fmaf(-m1, p0, invd1 * r1);
        s0 = x0; s1 = x1;
    }
    if (c_raw <= 64) {
        float* dst = g_M + (size_t)bc * NSTATE * MSTR;
        dst[(size_t)i0 * MSTR + c] = s0;
        dst[(size_t)i1 * MSTR + c] = s1;
    }
}

// ---------------- Phase B ----------------
__global__ __launch_bounds__(256) void scanB_kernel() {
    int b = blockIdx.x, tid = threadIdx.x;
    int i = tid >> 2, p = tid & 3;
    __shared__ __align__(16) float ss[64];
    if (tid < 64) ss[tid] = 0.f;
    __syncthreads();
    const float* rowp = g_M + ((size_t)(b * NCHUNK) * NSTATE + i) * MSTR;
    const size_t cstep = (size_t)NSTATE * MSTR;
    float4 m[4]; float vv;
    #pragma unroll
    for (int q = 0; q < 4; q++) m[q] = *(const float4*)(rowp + p * 16 + q * 4);
    vv = rowp[64];
    for (int k = 0; k < NCHUNK; k++) {
        if (p == 0) g_sinit[(size_t)(b * NCHUNK + k) * NSTATE + i] = ss[i];
        float4 mn[4]; float vn;
        const float* np = rowp + (size_t)(k + 1) * cstep;
        #pragma unroll
        for (int q = 0; q < 4; q++) mn[q] = *(const float4*)(np + p * 16 + q * 4);
        vn = np[64];
        float part = 0.f;
        #pragma unroll
        for (int q = 0; q < 4; q++) {
            float4 sv = *(const float4*)(ss + p * 16 + q * 4);
            part += m[q].x * sv.x + m[q].y * sv.y + m[q].z * sv.z + m[q].w * sv.w;
        }
        part += __shfl_xor_sync(0xffffffffu, part, 1);
        part += __shfl_xor_sync(0xffffffffu, part, 2);
        __syncthreads();
        if (p == 0) ss[i] = part + vv;
        __syncthreads();
        #pragma unroll
        for (int q = 0; q < 4; q++) m[q] = mn[q];
        vv = vn;
    }
}

// ---------------- Phase C ----------------
__global__ __launch_bounds__(32) void scanC_kernel(const float* __restrict__ Bm,
                                                   const float* __restrict__ Cm,
                                                   const float* __restrict__ A) {
    int bc = blockIdx.x, l = threadIdx.x;
    int i0 = 2 * l, i1 = 2 * l + 1;
    float e0 =  sqrtf(-A[i0 * 64 + i0]);
    float e1 = -sqrtf(-A[i1 * 64 + i1]);
    float e0sq = e0 * e0, e1sq = e1 * e1;
    float bv0 = Bm[(size_t)i0 * INNER], bv1 = Bm[(size_t)i1 * INNER];
    float C0 = Cm[i0], C1 = Cm[i1];
    float s0 = g_sinit[(size_t)bc * NSTATE + i0];
    float s1 = g_sinit[(size_t)bc * NSTATE + i1];
    __shared__ float sdt[CLEN], sS[CLEN];
    size_t tbase = (size_t)bc * CLEN;
    sdt[l] = g_dt[tbase + l];
    sS[l]  = g_S[tbase + l];
    __syncwarp();
    for (int t = 0; t < CLEN; t++) {
        float dt = sdt[t], S = sS[t];
        float invd0 = __fdividef(1.f, fmaf(dt, e0sq, 1.f));
        float invd1 = __fdividef(1.f, fmaf(dt, e1sq, 1.f));
        float k0 = e0 * invd0, k1 = e1 * invd1;
        float m0 = dt * k0,    m1 = dt * k1;
        float dtS = dt * S;
        float r0 = fmaf(dtS, bv0, s0);
        float r1 = fmaf(dtS, bv1, s1);
        float Bc = fmaf(invd1, k0 * r0, k1 * r1);
        float Ac = invd0 * invd1;
        #pragma unroll
        for (int ofs = 1; ofs < 32; ofs <<= 1) {
            float Au = __shfl_up_sync(0xffffffffu, Ac, ofs);
            float Bu = __shfl_up_sync(0xffffffffu, Bc, ofs);
            if (l >= ofs) { Bc = fmaf(Ac, Bu, Bc); Ac *= Au; }
        }
        float pex = __shfl_up_sync(0xffffffffu, Bc, 1);
        if (l == 0) pex = 0.f;
        float x0 = fmaf(-m0, pex, invd0 * r0);
        float p0 = fmaf(invd0, pex, k0 * r0);
        float x1 = fmaf(-m1, p0, invd1 * r1);
        s0 = x0; s1 = x1;
        float wv = C0 * x0 + C1 * x1;
        #pragma unroll
        for (int o = 16; o; o >>= 1) wv += __shfl_xor_sync(0xffffffffu, wv, o);
        if (l == 0) g_ysc[tbase + t] = wv;
    }
}

// ---------------- GEMM2: out = x + ysc * (g_gate @ WoT^T) ----------------
__global__ __launch_bounds__(256, 2) void gemm2_mma(const float* __restrict__ x,
                                                    float* __restrict__ out) {
    int tid = threadIdx.x, wid = tid >> 5, lane = tid & 31;
    int m0 = blockIdx.y * 128, n0 = blockIdx.x * 128;
    int wm = (wid >> 2) * 64, wn = (wid & 3) * 32;
    int grp = lane >> 2, tg = lane & 3;
    float acc[4][4][4] = {};
    gemm_body<24>(g_gate, INNER, g_WoT, INNER, m0, n0, acc);
    #pragma unroll
    for (int mi = 0; mi < 4; mi++) {
        int rr = m0 + wm + mi * 16 + grp;
        float ys0 = g_ysc[rr], ys1 = g_ysc[rr + 8];
        #pragma unroll
        for (int ni = 0; ni < 4; ni++) {
            int cc = n0 + wn + ni * 8 + 2 * tg;
            float2 x0 = *(const float2*)&x[(size_t)rr * 512 + cc];
            float2 x1 = *(const float2*)&x[(size_t)(rr + 8) * 512 + cc];
            float2 lo = {x0.x + ys0 * acc[mi][ni][0], x0.y + ys0 * acc[mi][ni][1]};
            float2 hi = {x1.x + ys1 * acc[mi][ni][2], x1.y + ys1 * acc[mi][ni][3]};
            *(float2*)&out[(size_t)rr * 512 + cc] = lo;
            *(float2*)&out[(size_t)(rr + 8) * 512 + cc] = hi;
        }
    }
}

// ---------------- launch ----------------
extern "C" void kernel_launch(void* const* d_in, const int* in_sizes, int n_in,
                              void* d_out, int out_size) {
    const float* x  = (const float*)d_in[0];
    const float* nw = (const float*)d_in[1];
    const float* nb = (const float*)d_in[2];
    const float* Wi = (const float*)d_in[3];
    const float* cw = (const float*)d_in[4];
    const float* A  = (const float*)d_in[5];
    const float* Bm = (const float*)d_in[6];
    const float* Cm = (const float*)d_in[7];
    const float* Wo = (const float*)d_in[8];
    float* out = (float*)d_out;

    cudaFuncSetAttribute(gemm1_mma, cudaFuncAttributeMaxDynamicSharedMemorySize, GEMM_SMEM);
    cudaFuncSetAttribute(gemm2_mma, cudaFuncAttributeMaxDynamicSharedMemorySize, GEMM_SMEM);

    __half* WiT; cudaGetSymbolAddress((void**)&WiT, g_WiT);
    __half* WoT; cudaGetSymbolAddress((void**)&WoT, g_WoT);

    ln_kernel<<<NROWS, 128>>>(x, nw, nb);
    transpose_kernel<<<dim3(72, 16), 256>>>(Wi, WiT, 512, 2304);
    transpose_kernel<<<dim3(16, 24), 256>>>(Wo, WoT, 768, 512);
    gemm1_mma<<<dim3(18, 128), 256, GEMM_SMEM>>>();
    conv_kernel<<<NROWS, 256>>>(cw);
    scanA_kernel<<<dim3(NBC, 17), 128>>>(Bm, A);
    scanB_kernel<<<BSZ, 256>>>();
    scanC_kernel<<<NBC, 32>>>(Bm, Cm, A);
    gemm2_mma<<<dim3(4, 128), 256, GEMM_SMEM>>>(x, out);
}